// round 14
// baseline (speedup 1.0000x reference)
#include <cuda_runtime.h>
#include <cuda_fp16.h>
#include <math.h>
#include <stdint.h>

#define NN 50000
#define NE 800000
#define H1 4
#define D1 64
#define NSPLIT 25088   // node/row split point (multiple of 128 and 8)

// ---------------- scratch (device globals; no runtime allocation) -------------
__device__ __half g_ft1h[NN * 256];
__device__ __half g_h1h [NN * 256];
__device__ __half g_ft2h[NN * 64];
__device__ float  g_res2[NN * 64];
__device__ float  g_el1[NN * 4];
__device__ float  g_er1[NN * 4];
__device__ float  g_el2[NN];
__device__ float  g_er2[NN];
__device__ int    g_deg[NN];
__device__ int    g_pos[NE];
__device__ int    g_offs[NN + 1];
__device__ int    g_bsum[128];
__device__ int    g_ssrc[NE];
__device__ float  g_abuf[NE * 4];

#define SCAN_NB ((NN + 511) / 512)

// ---------------- CSR build kernels --------------------------------------------
__global__ void hist_kernel(const int* __restrict__ dst, int* __restrict__ deg,
                            int* __restrict__ pos) {
    int e = blockIdx.x * blockDim.x + threadIdx.x;
    if (e < NE) pos[e] = atomicAdd(&deg[dst[e]], 1);
}

__global__ void scanA_kernel(const int* __restrict__ deg, int* __restrict__ bsum) {
    __shared__ int sm[256];
    int b = blockIdx.x, t = threadIdx.x;
    int i0 = b * 512 + t, i1 = i0 + 256;
    int v = 0;
    if (i0 < NN) v += deg[i0];
    if (i1 < NN) v += deg[i1];
    sm[t] = v;
    __syncthreads();
#pragma unroll
    for (int o = 128; o; o >>= 1) { if (t < o) sm[t] += sm[t + o]; __syncthreads(); }
    if (t == 0) bsum[b] = sm[0];
}

__global__ void scanB_kernel(const int* __restrict__ deg, const int* __restrict__ bsum,
                             int* __restrict__ offs) {
    __shared__ int sb[128];
    __shared__ int sm[256];
    int b = blockIdx.x, t = threadIdx.x;

    if (t < 128) sb[t] = (t < SCAN_NB) ? bsum[t] : 0;
    __syncthreads();
#pragma unroll
    for (int o = 1; o < 128; o <<= 1) {
        int x = 0;
        if (t < 128 && t >= o) x = sb[t - o];
        __syncthreads();
        if (t < 128) sb[t] += x;
        __syncthreads();
    }
    int bprefix = (b == 0) ? 0 : sb[b - 1];

    int i = b * 512 + t * 2;
    int d0 = (i < NN) ? deg[i] : 0;
    int d1 = (i + 1 < NN) ? deg[i + 1] : 0;
    int s = d0 + d1;
    sm[t] = s;
    __syncthreads();
#pragma unroll
    for (int o = 1; o < 256; o <<= 1) {
        int x = (t >= o) ? sm[t - o] : 0;
        __syncthreads();
        sm[t] += x;
        __syncthreads();
    }
    int ex = sm[t] - s + bprefix;
    if (i < NN) offs[i] = ex;
    if (i + 1 < NN) offs[i + 1] = ex + d0;
    if (b == 0 && t == 0) offs[NN] = NE;
}

__global__ void scatter_kernel(const int* __restrict__ src, const int* __restrict__ dst,
                               const int* __restrict__ offs, const int* __restrict__ pos,
                               int* __restrict__ ssrc) {
    int e = blockIdx.x * blockDim.x + threadIdx.x;
    if (e < NE) {
        ssrc[offs[dst[e]] + pos[e]] = src[e];
    }
}

// ---------------- fp16 tensor-core GEMM with fused attn epilogue --------------
#define GBM 128
#define GBN 64
#define GBK 32
#define AHS 40

__device__ __forceinline__ void mma_f16(float* c, const uint32_t* a, const uint32_t* b) {
    asm volatile(
        "mma.sync.aligned.m16n8k16.row.col.f32.f16.f16.f32 "
        "{%0,%1,%2,%3}, {%4,%5,%6,%7}, {%8,%9}, {%0,%1,%2,%3};\n"
        : "+f"(c[0]), "+f"(c[1]), "+f"(c[2]), "+f"(c[3])
        : "r"(a[0]), "r"(a[1]), "r"(a[2]), "r"(a[3]), "r"(b[0]), "r"(b[1]));
}

// ---- layer-1 GEMM: fp32 A, double-buffered half tiles ----
__global__ __launch_bounds__(256)
void gemm_attn_kernel(const float* __restrict__ A, const float* __restrict__ B,
                      __half* __restrict__ Ch,
                      int M, int Nc, int K,
                      const float* __restrict__ al, const float* __restrict__ ar,
                      float* __restrict__ el, float* __restrict__ er, int H) {
    __shared__ __half As[2][GBM][AHS];
    __shared__ __half Bs[2][GBN][AHS];

    int tid = threadIdx.x;
    int warp = tid >> 5, lane = tid & 31;
    int g = lane >> 2, tig = lane & 3;
    int m0 = blockIdx.x * GBM, n0 = blockIdx.y * GBN;
    int warp_row = (warp >> 1) * 32;
    int warp_col = (warp & 1) * 32;

    int a_row = tid >> 3;
    int a_col = (tid & 7) * 4;
    int b_row = tid >> 4;
    int b_col = (tid & 15) * 4;

    float c[2][4][4];
#pragma unroll
    for (int mi = 0; mi < 2; mi++)
#pragma unroll
        for (int ni = 0; ni < 4; ni++)
#pragma unroll
            for (int r = 0; r < 4; r++) c[mi][ni][r] = 0.f;

    const int nIter = K / GBK;
    float4 aP[4];
    float4 bP[2];

#pragma unroll
    for (int r = 0; r < 4; r++) {
        int m = m0 + a_row + r * 32;
        aP[r] = make_float4(0.f, 0.f, 0.f, 0.f);
        if (m < M) aP[r] = *(const float4*)(A + (size_t)m * K + a_col);
    }
#pragma unroll
    for (int r = 0; r < 2; r++)
        bP[r] = *(const float4*)(B + (size_t)(b_row + r * 16) * Nc + n0 + b_col);

#pragma unroll
    for (int r = 0; r < 4; r++) {
        int row = a_row + r * 32;
        *(__half2*)&As[0][row][a_col]     = __floats2half2_rn(aP[r].x, aP[r].y);
        *(__half2*)&As[0][row][a_col + 2] = __floats2half2_rn(aP[r].z, aP[r].w);
    }
#pragma unroll
    for (int r = 0; r < 2; r++) {
        int k = b_row + r * 16;
        Bs[0][b_col + 0][k] = __float2half(bP[r].x);
        Bs[0][b_col + 1][k] = __float2half(bP[r].y);
        Bs[0][b_col + 2][k] = __float2half(bP[r].z);
        Bs[0][b_col + 3][k] = __float2half(bP[r].w);
    }
    __syncthreads();

    for (int it = 0; it < nIter; it++) {
        int cb = it & 1;
        if (it + 1 < nIter) {
            int k0 = (it + 1) * GBK;
#pragma unroll
            for (int r = 0; r < 4; r++) {
                int m = m0 + a_row + r * 32;
                aP[r] = make_float4(0.f, 0.f, 0.f, 0.f);
                if (m < M) aP[r] = *(const float4*)(A + (size_t)m * K + k0 + a_col);
            }
#pragma unroll
            for (int r = 0; r < 2; r++)
                bP[r] = *(const float4*)(B + (size_t)(k0 + b_row + r * 16) * Nc + n0 + b_col);
        }

#pragma unroll
        for (int kk = 0; kk < GBK; kk += 16) {
            uint32_t a[2][4], b[4][2];
#pragma unroll
            for (int mi = 0; mi < 2; mi++) {
                int r0 = warp_row + mi * 16 + g;
                a[mi][0] = *(const uint32_t*)&As[cb][r0][kk + 2 * tig];
                a[mi][1] = *(const uint32_t*)&As[cb][r0 + 8][kk + 2 * tig];
                a[mi][2] = *(const uint32_t*)&As[cb][r0][kk + 2 * tig + 8];
                a[mi][3] = *(const uint32_t*)&As[cb][r0 + 8][kk + 2 * tig + 8];
            }
#pragma unroll
            for (int ni = 0; ni < 4; ni++) {
                int col = warp_col + ni * 8 + g;
                b[ni][0] = *(const uint32_t*)&Bs[cb][col][kk + 2 * tig];
                b[ni][1] = *(const uint32_t*)&Bs[cb][col][kk + 2 * tig + 8];
            }
#pragma unroll
            for (int mi = 0; mi < 2; mi++)
#pragma unroll
                for (int ni = 0; ni < 4; ni++)
                    mma_f16(c[mi][ni], a[mi], b[ni]);
        }

        if (it + 1 < nIter) {
            int nb = cb ^ 1;
#pragma unroll
            for (int r = 0; r < 4; r++) {
                int row = a_row + r * 32;
                *(__half2*)&As[nb][row][a_col]     = __floats2half2_rn(aP[r].x, aP[r].y);
                *(__half2*)&As[nb][row][a_col + 2] = __floats2half2_rn(aP[r].z, aP[r].w);
            }
#pragma unroll
            for (int r = 0; r < 2; r++) {
                int k = b_row + r * 16;
                Bs[nb][b_col + 0][k] = __float2half(bP[r].x);
                Bs[nb][b_col + 1][k] = __float2half(bP[r].y);
                Bs[nb][b_col + 2][k] = __float2half(bP[r].z);
                Bs[nb][b_col + 3][k] = __float2half(bP[r].w);
            }
            __syncthreads();
        }
    }

#pragma unroll
    for (int mi = 0; mi < 2; mi++)
#pragma unroll
        for (int ni = 0; ni < 4; ni++) {
            int row = m0 + warp_row + mi * 16 + g;
            int col = n0 + warp_col + ni * 8 + tig * 2;
            if (row < M)
                *(__half2*)(Ch + (size_t)row * Nc + col) =
                    __floats2half2_rn(c[mi][ni][0], c[mi][ni][1]);
            if (row + 8 < M)
                *(__half2*)(Ch + (size_t)(row + 8) * Nc + col) =
                    __floats2half2_rn(c[mi][ni][2], c[mi][ni][3]);
        }

    if (al != nullptr) {
        int head = blockIdx.y;
        const float* alh = al + head * 64;
        const float* arh = ar + head * 64;
        float pel[2][2], per_[2][2];
#pragma unroll
        for (int mi = 0; mi < 2; mi++) { pel[mi][0] = pel[mi][1] = per_[mi][0] = per_[mi][1] = 0.f; }
#pragma unroll
        for (int ni = 0; ni < 4; ni++) {
#pragma unroll
            for (int j = 0; j < 2; j++) {
                int col = warp_col + ni * 8 + tig * 2 + j;
                float wl = alh[col], wr = arh[col];
#pragma unroll
                for (int mi = 0; mi < 2; mi++) {
                    pel[mi][0] += c[mi][ni][j] * wl;
                    per_[mi][0] += c[mi][ni][j] * wr;
                    pel[mi][1] += c[mi][ni][2 + j] * wl;
                    per_[mi][1] += c[mi][ni][2 + j] * wr;
                }
            }
        }
#pragma unroll
        for (int off = 1; off < 4; off <<= 1) {
#pragma unroll
            for (int mi = 0; mi < 2; mi++)
#pragma unroll
                for (int rh = 0; rh < 2; rh++) {
                    pel[mi][rh] += __shfl_xor_sync(0xffffffffu, pel[mi][rh], off);
                    per_[mi][rh] += __shfl_xor_sync(0xffffffffu, per_[mi][rh], off);
                }
        }
        __syncthreads();
        float (*sred)[4] = (float (*)[4])&As[0][0][0];
        int half = warp & 1;
        if (tig == 0) {
#pragma unroll
            for (int mi = 0; mi < 2; mi++) {
#pragma unroll
                for (int rh = 0; rh < 2; rh++) {
                    int row = warp_row + mi * 16 + rh * 8 + g;
                    sred[row][half]     = pel[mi][rh];
                    sred[row][2 + half] = per_[mi][rh];
                }
            }
        }
        __syncthreads();
        if (tid < 128) {
            int m = m0 + tid;
            if (m < M) {
                el[(size_t)m * H + head] = sred[tid][0] + sred[tid][1];
                er[(size_t)m * H + head] = sred[tid][2] + sred[tid][3];
            }
        }
    }
}

// ---- layer-2 GEMM: fp16 A direct, fp16/fp32 output, row-range [mStart, M) ----
__global__ __launch_bounds__(256)
void gemm_h_attn_kernel(const __half* __restrict__ Ah, const float* __restrict__ B,
                        float* __restrict__ C, __half* __restrict__ Ch,
                        int mStart, int M, int Nc, int K,
                        const float* __restrict__ al, const float* __restrict__ ar,
                        float* __restrict__ el, float* __restrict__ er, int H) {
    __shared__ __half As[GBM][AHS];
    __shared__ __half Bs[GBN][AHS];
    int tid = threadIdx.x;
    int warp = tid >> 5, lane = tid & 31;
    int g = lane >> 2, tig = lane & 3;
    int m0 = mStart + blockIdx.x * GBM, n0 = blockIdx.y * GBN;
    int warp_row = (warp >> 1) * 32;
    int warp_col = (warp & 1) * 32;

    int ar_ = tid >> 2;
    int ac8 = (tid & 3) * 8;
    int b_row = tid >> 4;
    int b_col = (tid & 15) * 4;

    float c[2][4][4];
#pragma unroll
    for (int mi = 0; mi < 2; mi++)
#pragma unroll
        for (int ni = 0; ni < 4; ni++)
#pragma unroll
            for (int r = 0; r < 4; r++) c[mi][ni][r] = 0.f;

    for (int k0 = 0; k0 < K; k0 += GBK) {
#pragma unroll
        for (int hh = 0; hh < 2; hh++) {
            int row = ar_ + hh * 64;
            int m = m0 + row;
            uint4 u = make_uint4(0, 0, 0, 0);
            if (m < M) u = *(const uint4*)(Ah + (size_t)m * K + k0 + ac8);
            *(uint4*)&As[row][ac8] = u;
        }
#pragma unroll
        for (int r = 0; r < 2; r++) {
            int k = b_row + r * 16;
            float4 v = *(const float4*)(B + (size_t)(k0 + k) * Nc + n0 + b_col);
            Bs[b_col + 0][k] = __float2half(v.x);
            Bs[b_col + 1][k] = __float2half(v.y);
            Bs[b_col + 2][k] = __float2half(v.z);
            Bs[b_col + 3][k] = __float2half(v.w);
        }
        __syncthreads();
#pragma unroll
        for (int kk = 0; kk < GBK; kk += 16) {
            uint32_t a[2][4], b[4][2];
#pragma unroll
            for (int mi = 0; mi < 2; mi++) {
                int r0 = warp_row + mi * 16 + g;
                a[mi][0] = *(const uint32_t*)&As[r0][kk + 2 * tig];
                a[mi][1] = *(const uint32_t*)&As[r0 + 8][kk + 2 * tig];
                a[mi][2] = *(const uint32_t*)&As[r0][kk + 2 * tig + 8];
                a[mi][3] = *(const uint32_t*)&As[r0 + 8][kk + 2 * tig + 8];
            }
#pragma unroll
            for (int ni = 0; ni < 4; ni++) {
                int col = warp_col + ni * 8 + g;
                b[ni][0] = *(const uint32_t*)&Bs[col][kk + 2 * tig];
                b[ni][1] = *(const uint32_t*)&Bs[col][kk + 2 * tig + 8];
            }
#pragma unroll
            for (int mi = 0; mi < 2; mi++)
#pragma unroll
                for (int ni = 0; ni < 4; ni++)
                    mma_f16(c[mi][ni], a[mi], b[ni]);
        }
        __syncthreads();
    }

#pragma unroll
    for (int mi = 0; mi < 2; mi++)
#pragma unroll
        for (int ni = 0; ni < 4; ni++) {
            int row = m0 + warp_row + mi * 16 + g;
            int col = n0 + warp_col + ni * 8 + tig * 2;
            if (Ch != nullptr) {
                if (row < M)
                    *(__half2*)(Ch + (size_t)row * Nc + col) =
                        __floats2half2_rn(c[mi][ni][0], c[mi][ni][1]);
                if (row + 8 < M)
                    *(__half2*)(Ch + (size_t)(row + 8) * Nc + col) =
                        __floats2half2_rn(c[mi][ni][2], c[mi][ni][3]);
            } else {
                if (row < M)
                    *(float2*)(C + (size_t)row * Nc + col) =
                        make_float2(c[mi][ni][0], c[mi][ni][1]);
                if (row + 8 < M)
                    *(float2*)(C + (size_t)(row + 8) * Nc + col) =
                        make_float2(c[mi][ni][2], c[mi][ni][3]);
            }
        }

    if (al != nullptr) {
        int head = blockIdx.y;
        const float* alh = al + head * 64;
        const float* arh = ar + head * 64;
        float pel[2][2], per_[2][2];
#pragma unroll
        for (int mi = 0; mi < 2; mi++) { pel[mi][0] = pel[mi][1] = per_[mi][0] = per_[mi][1] = 0.f; }
#pragma unroll
        for (int ni = 0; ni < 4; ni++) {
#pragma unroll
            for (int j = 0; j < 2; j++) {
                int col = warp_col + ni * 8 + tig * 2 + j;
                float wl = alh[col], wr = arh[col];
#pragma unroll
                for (int mi = 0; mi < 2; mi++) {
                    pel[mi][0] += c[mi][ni][j] * wl;
                    per_[mi][0] += c[mi][ni][j] * wr;
                    pel[mi][1] += c[mi][ni][2 + j] * wl;
                    per_[mi][1] += c[mi][ni][2 + j] * wr;
                }
            }
        }
#pragma unroll
        for (int off = 1; off < 4; off <<= 1) {
#pragma unroll
            for (int mi = 0; mi < 2; mi++)
#pragma unroll
                for (int rh = 0; rh < 2; rh++) {
                    pel[mi][rh] += __shfl_xor_sync(0xffffffffu, pel[mi][rh], off);
                    per_[mi][rh] += __shfl_xor_sync(0xffffffffu, per_[mi][rh], off);
                }
        }
        __syncthreads();
        float (*sred)[4] = (float (*)[4])&As[0][0];
        int half = warp & 1;
        if (tig == 0) {
#pragma unroll
            for (int mi = 0; mi < 2; mi++) {
#pragma unroll
                for (int rh = 0; rh < 2; rh++) {
                    int row = warp_row + mi * 16 + rh * 8 + g;
                    sred[row][half]     = pel[mi][rh];
                    sred[row][2 + half] = per_[mi][rh];
                }
            }
        }
        __syncthreads();
        if (tid < 128) {
            int m = m0 + tid;
            if (m < M) {
                el[(size_t)m * H + head] = sred[tid][0] + sred[tid][1];
                er[(size_t)m * H + head] = sred[tid][2] + sred[tid][3];
            }
        }
    }
}

__device__ __forceinline__ float lrelu(float x) { return x > 0.f ? x : 0.2f * x; }

// ---------------- layer-1 aggregation: node range [nodeStart, nodeEnd) --------
__global__ __launch_bounds__(256)
void aggr1_kernel(const int* __restrict__ offs, const int* __restrict__ ssrc,
                  const __half* __restrict__ fth, const float* __restrict__ el,
                  const float* __restrict__ er, const float* __restrict__ bias,
                  float* __restrict__ abuf, __half* __restrict__ h1,
                  int nodeStart, int nodeEnd) {
    int n = nodeStart + ((blockIdx.x * blockDim.x + threadIdx.x) >> 5);
    int lane = threadIdx.x & 31;
    if (n >= nodeEnd) return;
    int beg = offs[n], end = offs[n + 1];
    int deg = end - beg;
    int h = lane >> 3;
    int cbase = lane * 8;
    float acc[8] = {0.f, 0.f, 0.f, 0.f, 0.f, 0.f, 0.f, 0.f};

    if (deg > 0 && deg <= 32) {
        float4 ern = *(const float4*)(er + (size_t)n * 4);
        int s_mine = 0;
        float4 ee = make_float4(0.f, 0.f, 0.f, 0.f);
        if (lane < deg) {
            s_mine = __ldg(ssrc + beg + lane);
            float4 e = *(const float4*)(el + (size_t)s_mine * 4);
            e.x = lrelu(e.x + ern.x); e.y = lrelu(e.y + ern.y);
            e.z = lrelu(e.z + ern.z); e.w = lrelu(e.w + ern.w);
            ee = make_float4(__expf(e.x), __expf(e.y), __expf(e.z), __expf(e.w));
            ((float4*)abuf)[beg + lane] = ee;
        }
        float4 ds = ee;
#pragma unroll
        for (int o = 16; o; o >>= 1) {
            ds.x += __shfl_xor_sync(0xffffffffu, ds.x, o);
            ds.y += __shfl_xor_sync(0xffffffffu, ds.y, o);
            ds.z += __shfl_xor_sync(0xffffffffu, ds.z, o);
            ds.w += __shfl_xor_sync(0xffffffffu, ds.w, o);
        }
        float dh = (h == 0) ? ds.x : (h == 1) ? ds.y : (h == 2) ? ds.z : ds.w;
        float invh = 1.0f / dh;
        __syncwarp();

        int j = 0;
        for (; j + 1 < deg; j += 2) {
            int s0 = __shfl_sync(0xffffffffu, s_mine, j);
            int s1 = __shfl_sync(0xffffffffu, s_mine, j + 1);
            float a0 = __ldg(abuf + (size_t)(beg + j) * 4 + h) * invh;
            float a1 = __ldg(abuf + (size_t)(beg + j + 1) * 4 + h) * invh;
            uint4 u0 = __ldg((const uint4*)(fth + (size_t)s0 * 256) + lane);
            uint4 u1 = __ldg((const uint4*)(fth + (size_t)s1 * 256) + lane);
            const __half2* h0 = (const __half2*)&u0;
            const __half2* h1p = (const __half2*)&u1;
#pragma unroll
            for (int q = 0; q < 4; q++) {
                float2 f0 = __half22float2(h0[q]);
                float2 f1 = __half22float2(h1p[q]);
                acc[2 * q]     += a0 * f0.x + a1 * f1.x;
                acc[2 * q + 1] += a0 * f0.y + a1 * f1.y;
            }
        }
        if (j < deg) {
            int s0 = __shfl_sync(0xffffffffu, s_mine, j);
            float a0 = __ldg(abuf + (size_t)(beg + j) * 4 + h) * invh;
            uint4 u0 = __ldg((const uint4*)(fth + (size_t)s0 * 256) + lane);
            const __half2* h0 = (const __half2*)&u0;
#pragma unroll
            for (int q = 0; q < 4; q++) {
                float2 f0 = __half22float2(h0[q]);
                acc[2 * q]     += a0 * f0.x;
                acc[2 * q + 1] += a0 * f0.y;
            }
        }
    } else if (deg > 32) {
        float4 ern = *(const float4*)(er + (size_t)n * 4);
        float4 ds = make_float4(0.f, 0.f, 0.f, 0.f);
        for (int i = beg + lane; i < end; i += 32) {
            int s = __ldg(ssrc + i);
            float4 e = *(const float4*)(el + (size_t)s * 4);
            e.x = lrelu(e.x + ern.x); e.y = lrelu(e.y + ern.y);
            e.z = lrelu(e.z + ern.z); e.w = lrelu(e.w + ern.w);
            float4 ee = make_float4(__expf(e.x), __expf(e.y), __expf(e.z), __expf(e.w));
            ((float4*)abuf)[i] = ee;
            ds.x += ee.x; ds.y += ee.y; ds.z += ee.z; ds.w += ee.w;
        }
#pragma unroll
        for (int o = 16; o; o >>= 1) {
            ds.x += __shfl_xor_sync(0xffffffffu, ds.x, o);
            ds.y += __shfl_xor_sync(0xffffffffu, ds.y, o);
            ds.z += __shfl_xor_sync(0xffffffffu, ds.z, o);
            ds.w += __shfl_xor_sync(0xffffffffu, ds.w, o);
        }
        float dh = (h == 0) ? ds.x : (h == 1) ? ds.y : (h == 2) ? ds.z : ds.w;
        float invh = 1.0f / dh;
        __syncwarp();
        int i = beg;
        for (; i + 1 < end; i += 2) {
            int s0 = __ldg(ssrc + i);
            int s1 = __ldg(ssrc + i + 1);
            float a0 = __ldg(abuf + (size_t)i * 4 + h) * invh;
            float a1 = __ldg(abuf + (size_t)(i + 1) * 4 + h) * invh;
            uint4 u0 = __ldg((const uint4*)(fth + (size_t)s0 * 256) + lane);
            uint4 u1 = __ldg((const uint4*)(fth + (size_t)s1 * 256) + lane);
            const __half2* h0 = (const __half2*)&u0;
            const __half2* h1p = (const __half2*)&u1;
#pragma unroll
            for (int q = 0; q < 4; q++) {
                float2 f0 = __half22float2(h0[q]);
                float2 f1 = __half22float2(h1p[q]);
                acc[2 * q]     += a0 * f0.x + a1 * f1.x;
                acc[2 * q + 1] += a0 * f0.y + a1 * f1.y;
            }
        }
        if (i < end) {
            int s0 = __ldg(ssrc + i);
            float a0 = __ldg(abuf + (size_t)i * 4 + h) * invh;
            uint4 u0 = __ldg((const uint4*)(fth + (size_t)s0 * 256) + lane);
            const __half2* h0 = (const __half2*)&u0;
#pragma unroll
            for (int q = 0; q < 4; q++) {
                float2 f0 = __half22float2(h0[q]);
                acc[2 * q]     += a0 * f0.x;
                acc[2 * q + 1] += a0 * f0.y;
            }
        }
    }
    float4 b0 = *(const float4*)(bias + cbase);
    float4 b1v = *(const float4*)(bias + cbase + 4);
    float bv[8] = {b0.x, b0.y, b0.z, b0.w, b1v.x, b1v.y, b1v.z, b1v.w};
    float o[8];
#pragma unroll
    for (int j = 0; j < 8; j++) {
        float x = acc[j] + bv[j];
        o[j] = x > 0.f ? x : expm1f(x);      // ELU
    }
    __half2 ho[4];
#pragma unroll
    for (int j = 0; j < 4; j++) ho[j] = __floats2half2_rn(o[2 * j], o[2 * j + 1]);
    *(uint4*)(h1 + (size_t)n * 256 + cbase) = *(uint4*)ho;
}

// ---------------- layer-2 aggregation: warp per node, register-resident edges -
__global__ __launch_bounds__(256)
void aggr2_kernel(const int* __restrict__ offs, const int* __restrict__ ssrc,
                  const __half* __restrict__ fth, const float* __restrict__ el,
                  const float* __restrict__ er, const float* __restrict__ res,
                  const float* __restrict__ bias, float* __restrict__ abuf,
                  float* __restrict__ out) {
    int n = (blockIdx.x * blockDim.x + threadIdx.x) >> 5;
    int lane = threadIdx.x & 31;
    if (n >= NN) return;
    int beg = offs[n], end = offs[n + 1];
    int deg = end - beg;
    float2 acc = make_float2(0.f, 0.f);

    if (deg > 0 && deg <= 32) {
        float ern = er[n];
        int s_mine = 0;
        float ee = 0.f;
        if (lane < deg) {
            s_mine = __ldg(ssrc + beg + lane);
            ee = __expf(lrelu(__ldg(el + s_mine) + ern));
        }
        float dsum = ee;
#pragma unroll
        for (int o = 16; o; o >>= 1) dsum += __shfl_xor_sync(0xffffffffu, dsum, o);
        float inv = 1.0f / dsum;

        int j = 0;
        for (; j + 1 < deg; j += 2) {
            int s0 = __shfl_sync(0xffffffffu, s_mine, j);
            int s1 = __shfl_sync(0xffffffffu, s_mine, j + 1);
            float a0 = __shfl_sync(0xffffffffu, ee, j) * inv;
            float a1 = __shfl_sync(0xffffffffu, ee, j + 1) * inv;
            __half2 v0 = __ldg((const __half2*)(fth + (size_t)s0 * 64) + lane);
            __half2 v1 = __ldg((const __half2*)(fth + (size_t)s1 * 64) + lane);
            float2 f0 = __half22float2(v0), f1 = __half22float2(v1);
            acc.x += a0 * f0.x + a1 * f1.x;
            acc.y += a0 * f0.y + a1 * f1.y;
        }
        if (j < deg) {
            int s0 = __shfl_sync(0xffffffffu, s_mine, j);
            float a0 = __shfl_sync(0xffffffffu, ee, j) * inv;
            float2 f0 = __half22float2(__ldg((const __half2*)(fth + (size_t)s0 * 64) + lane));
            acc.x += a0 * f0.x;
            acc.y += a0 * f0.y;
        }
    } else if (deg > 32) {
        float ern = er[n];
        float dsum = 0.f;
        for (int i = beg + lane; i < end; i += 32) {
            int s = __ldg(ssrc + i);
            float e = lrelu(__ldg(el + s) + ern);
            float ee = __expf(e);
            abuf[i] = ee;
            dsum += ee;
        }
#pragma unroll
        for (int o = 16; o; o >>= 1) dsum += __shfl_xor_sync(0xffffffffu, dsum, o);
        float inv = 1.0f / dsum;
        __syncwarp();
        int i = beg;
        for (; i + 1 < end; i += 2) {
            int s0 = __ldg(ssrc + i);
            int s1 = __ldg(ssrc + i + 1);
            float a0 = __ldg(abuf + i) * inv;
            float a1 = __ldg(abuf + i + 1) * inv;
            __half2 v0 = __ldg((const __half2*)(fth + (size_t)s0 * 64) + lane);
            __half2 v1 = __ldg((const __half2*)(fth + (size_t)s1 * 64) + lane);
            float2 f0 = __half22float2(v0), f1 = __half22float2(v1);
            acc.x += a0 * f0.x + a1 * f1.x;
            acc.y += a0 * f0.y + a1 * f1.y;
        }
        if (i < end) {
            int s0 = __ldg(ssrc + i);
            float a0 = __ldg(abuf + i) * inv;
            float2 f0 = __half22float2(__ldg((const __half2*)(fth + (size_t)s0 * 64) + lane));
            acc.x += a0 * f0.x;
            acc.y += a0 * f0.y;
        }
    }
    float2 r  = *(const float2*)(res + (size_t)n * 64 + lane * 2);
    float2 bb = *(const float2*)(bias + lane * 2);
    float2 o2 = make_float2(acc.x + r.x + bb.x, acc.y + r.y + bb.y);
    *(float2*)(out + (size_t)n * 64 + lane * 2) = o2;
}

// ---------------- launch ------------------------------------------------------
extern "C" void kernel_launch(void* const* d_in, const int* in_sizes, int n_in,
                              void* d_out, int out_size) {
    const float* feat  = (const float*)d_in[0];
    const int*   src   = (const int*)  d_in[1];
    const int*   dst   = (const int*)  d_in[2];
    const float* W1    = (const float*)d_in[3];
    const float* al1   = (const float*)d_in[4];
    const float* ar1   = (const float*)d_in[5];
    const float* b1    = (const float*)d_in[6];
    const float* W2    = (const float*)d_in[7];
    const float* al2   = (const float*)d_in[8];
    const float* ar2   = (const float*)d_in[9];
    const float* b2    = (const float*)d_in[10];
    const float* resW2 = (const float*)d_in[11];
    float* out = (float*)d_out;

    __half *ft1h, *ft2h, *h1h;
    float *res2, *el1, *er1, *el2, *er2, *abuf;
    int *deg, *pos, *offs, *ssrc, *bsum;
    cudaGetSymbolAddress((void**)&ft1h, g_ft1h);
    cudaGetSymbolAddress((void**)&h1h,  g_h1h);
    cudaGetSymbolAddress((void**)&ft2h, g_ft2h);
    cudaGetSymbolAddress((void**)&res2, g_res2);
    cudaGetSymbolAddress((void**)&el1,  g_el1);
    cudaGetSymbolAddress((void**)&er1,  g_er1);
    cudaGetSymbolAddress((void**)&el2,  g_el2);
    cudaGetSymbolAddress((void**)&er2,  g_er2);
    cudaGetSymbolAddress((void**)&abuf, g_abuf);
    cudaGetSymbolAddress((void**)&deg,  g_deg);
    cudaGetSymbolAddress((void**)&pos,  g_pos);
    cudaGetSymbolAddress((void**)&offs, g_offs);
    cudaGetSymbolAddress((void**)&ssrc, g_ssrc);
    cudaGetSymbolAddress((void**)&bsum, g_bsum);

    static cudaStream_t s1 = nullptr;
    static cudaEvent_t evA = nullptr, evB = nullptr, evH1 = nullptr,
                       evH2 = nullptr, evR = nullptr;
    if (s1 == nullptr) {
        cudaStreamCreateWithFlags(&s1, cudaStreamNonBlocking);
        cudaEventCreateWithFlags(&evA,  cudaEventDisableTiming);
        cudaEventCreateWithFlags(&evB,  cudaEventDisableTiming);
        cudaEventCreateWithFlags(&evH1, cudaEventDisableTiming);
        cudaEventCreateWithFlags(&evH2, cudaEventDisableTiming);
        cudaEventCreateWithFlags(&evR,  cudaEventDisableTiming);
    }

    const int TB = 256;
    const int GX = (NN + GBM - 1) / GBM;
    const int GX1 = NSPLIT / GBM;                       // 196
    const int GX2 = (NN - NSPLIT + GBM - 1) / GBM;      // 195
    const int AB1 = (NSPLIT * 32 + TB - 1) / TB;        // aggr1 half1 blocks
    const int AB2 = ((NN - NSPLIT) * 32 + TB - 1) / TB; // aggr1 half2 blocks

    // ---- fork: CSR build on s1, concurrent with layer-1 GEMM on stream 0 ----
    cudaEventRecord(evA, 0);
    cudaStreamWaitEvent(s1, evA, 0);

    cudaMemsetAsync(deg, 0, NN * sizeof(int), s1);
    hist_kernel<<<(NE + TB - 1) / TB, TB, 0, s1>>>(dst, deg, pos);
    scanA_kernel<<<SCAN_NB, 256, 0, s1>>>(deg, bsum);
    scanB_kernel<<<SCAN_NB, 256, 0, s1>>>(deg, bsum, offs);
    scatter_kernel<<<(NE + TB - 1) / TB, TB, 0, s1>>>(src, dst, offs, pos, ssrc);
    cudaEventRecord(evB, s1);

    gemm_attn_kernel<<<dim3(GX, 4), TB>>>(feat, W1, ft1h, NN, 256, 256,
                                          al1, ar1, el1, er1, H1);

    // ---- join: aggr1 needs both CSR and gemm1; run in two node halves ----
    cudaStreamWaitEvent(0, evB, 0);
    aggr1_kernel<<<AB1, TB>>>(offs, ssrc, ft1h, el1, er1, b1, abuf, h1h, 0, NSPLIT);
    cudaEventRecord(evH1, 0);
    aggr1_kernel<<<AB2, TB>>>(offs, ssrc, ft1h, el1, er1, b1, abuf, h1h, NSPLIT, NN);
    cudaEventRecord(evH2, 0);

    // ---- s1: layer-2 GEMMs for half1 overlap with aggr1 half2 ----
    cudaStreamWaitEvent(s1, evH1, 0);
    gemm_h_attn_kernel<<<dim3(GX1, 1), TB, 0, s1>>>(h1h, W2, nullptr, ft2h,
                                                    0, NSPLIT, 64, 256,
                                                    al2, ar2, el2, er2, 1);
    gemm_h_attn_kernel<<<dim3(GX1, 1), TB, 0, s1>>>(h1h, resW2, res2, nullptr,
                                                    0, NSPLIT, 64, 256,
                                                    nullptr, nullptr, nullptr, nullptr, 1);
    cudaStreamWaitEvent(s1, evH2, 0);
    gemm_h_attn_kernel<<<dim3(GX2, 1), TB, 0, s1>>>(h1h, resW2, res2, nullptr,
                                                    NSPLIT, NN, 64, 256,
                                                    nullptr, nullptr, nullptr, nullptr, 1);
    cudaEventRecord(evR, s1);

    // ---- s0: half2 W2 GEMM after aggr1 half2 ----
    gemm_h_attn_kernel<<<dim3(GX2, 1), TB>>>(h1h, W2, nullptr, ft2h,
                                             NSPLIT, NN, 64, 256,
                                             al2, ar2, el2, er2, 1);

    // ---- join: aggr2 needs all of ft2h/el2/er2 (s0) and res2 (s1) ----
    cudaStreamWaitEvent(0, evR, 0);
    aggr2_kernel<<<(NN * 32 + TB - 1) / TB, TB>>>(offs, ssrc, ft2h, el2, er2, res2, b2, abuf, out);
}

// round 15
// speedup vs baseline: 1.0589x; 1.0589x over previous
#include <cuda_runtime.h>
#include <cuda_fp16.h>
#include <math.h>
#include <stdint.h>

#define NN 50000
#define NE 800000
#define H1 4
#define D1 64

// ---------------- scratch (device globals; no runtime allocation) -------------
__device__ __half g_ft1h[NN * 256];
__device__ __half g_h1h [NN * 256];
__device__ __half g_ft2h[NN * 64];
__device__ float  g_res2[NN * 64];
__device__ float  g_el1[NN * 4];
__device__ float  g_er1[NN * 4];
__device__ float  g_el2[NN];
__device__ float  g_er2[NN];
__device__ int    g_deg[NN];
__device__ int    g_pos[NE];
__device__ int    g_offs[NN + 1];
__device__ int    g_bsum[128];
__device__ int    g_ssrc[NE];
__device__ float  g_abuf[NE * 4];

#define SCAN_NB ((NN + 511) / 512)

// ---------------- CSR build kernels --------------------------------------------
__global__ void hist_kernel(const int* __restrict__ dst, int* __restrict__ deg,
                            int* __restrict__ pos) {
    int e = blockIdx.x * blockDim.x + threadIdx.x;
    if (e < NE) pos[e] = atomicAdd(&deg[dst[e]], 1);
}

__global__ void scanA_kernel(const int* __restrict__ deg, int* __restrict__ bsum) {
    __shared__ int sm[256];
    int b = blockIdx.x, t = threadIdx.x;
    int i0 = b * 512 + t, i1 = i0 + 256;
    int v = 0;
    if (i0 < NN) v += deg[i0];
    if (i1 < NN) v += deg[i1];
    sm[t] = v;
    __syncthreads();
#pragma unroll
    for (int o = 128; o; o >>= 1) { if (t < o) sm[t] += sm[t + o]; __syncthreads(); }
    if (t == 0) bsum[b] = sm[0];
}

__global__ void scanB_kernel(const int* __restrict__ deg, const int* __restrict__ bsum,
                             int* __restrict__ offs) {
    __shared__ int sb[128];
    __shared__ int sm[256];
    int b = blockIdx.x, t = threadIdx.x;

    if (t < 128) sb[t] = (t < SCAN_NB) ? bsum[t] : 0;
    __syncthreads();
#pragma unroll
    for (int o = 1; o < 128; o <<= 1) {
        int x = 0;
        if (t < 128 && t >= o) x = sb[t - o];
        __syncthreads();
        if (t < 128) sb[t] += x;
        __syncthreads();
    }
    int bprefix = (b == 0) ? 0 : sb[b - 1];

    int i = b * 512 + t * 2;
    int d0 = (i < NN) ? deg[i] : 0;
    int d1 = (i + 1 < NN) ? deg[i + 1] : 0;
    int s = d0 + d1;
    sm[t] = s;
    __syncthreads();
#pragma unroll
    for (int o = 1; o < 256; o <<= 1) {
        int x = (t >= o) ? sm[t - o] : 0;
        __syncthreads();
        sm[t] += x;
        __syncthreads();
    }
    int ex = sm[t] - s + bprefix;
    if (i < NN) offs[i] = ex;
    if (i + 1 < NN) offs[i + 1] = ex + d0;
    if (b == 0 && t == 0) offs[NN] = NE;
}

__global__ void scatter_kernel(const int* __restrict__ src, const int* __restrict__ dst,
                               const int* __restrict__ offs, const int* __restrict__ pos,
                               int* __restrict__ ssrc) {
    int e = blockIdx.x * blockDim.x + threadIdx.x;
    if (e < NE) {
        ssrc[offs[dst[e]] + pos[e]] = src[e];
    }
}

// ---------------- fp16 tensor-core GEMM with fused attn epilogue --------------
#define GBM 128
#define GBN 64
#define GBK 32
#define AHS 40

__device__ __forceinline__ void mma_f16(float* c, const uint32_t* a, const uint32_t* b) {
    asm volatile(
        "mma.sync.aligned.m16n8k16.row.col.f32.f16.f16.f32 "
        "{%0,%1,%2,%3}, {%4,%5,%6,%7}, {%8,%9}, {%0,%1,%2,%3};\n"
        : "+f"(c[0]), "+f"(c[1]), "+f"(c[2]), "+f"(c[3])
        : "r"(a[0]), "r"(a[1]), "r"(a[2]), "r"(a[3]), "r"(b[0]), "r"(b[1]));
}

// ---- layer-1 GEMM: fp32 A, double-buffered half tiles ----
__global__ __launch_bounds__(256)
void gemm_attn_kernel(const float* __restrict__ A, const float* __restrict__ B,
                      __half* __restrict__ Ch,
                      int M, int Nc, int K,
                      const float* __restrict__ al, const float* __restrict__ ar,
                      float* __restrict__ el, float* __restrict__ er, int H) {
    __shared__ __half As[2][GBM][AHS];
    __shared__ __half Bs[2][GBN][AHS];

    int tid = threadIdx.x;
    int warp = tid >> 5, lane = tid & 31;
    int g = lane >> 2, tig = lane & 3;
    int m0 = blockIdx.x * GBM, n0 = blockIdx.y * GBN;
    int warp_row = (warp >> 1) * 32;
    int warp_col = (warp & 1) * 32;

    int a_row = tid >> 3;
    int a_col = (tid & 7) * 4;
    int b_row = tid >> 4;
    int b_col = (tid & 15) * 4;

    float c[2][4][4];
#pragma unroll
    for (int mi = 0; mi < 2; mi++)
#pragma unroll
        for (int ni = 0; ni < 4; ni++)
#pragma unroll
            for (int r = 0; r < 4; r++) c[mi][ni][r] = 0.f;

    const int nIter = K / GBK;
    float4 aP[4];
    float4 bP[2];

#pragma unroll
    for (int r = 0; r < 4; r++) {
        int m = m0 + a_row + r * 32;
        aP[r] = make_float4(0.f, 0.f, 0.f, 0.f);
        if (m < M) aP[r] = *(const float4*)(A + (size_t)m * K + a_col);
    }
#pragma unroll
    for (int r = 0; r < 2; r++)
        bP[r] = *(const float4*)(B + (size_t)(b_row + r * 16) * Nc + n0 + b_col);

#pragma unroll
    for (int r = 0; r < 4; r++) {
        int row = a_row + r * 32;
        *(__half2*)&As[0][row][a_col]     = __floats2half2_rn(aP[r].x, aP[r].y);
        *(__half2*)&As[0][row][a_col + 2] = __floats2half2_rn(aP[r].z, aP[r].w);
    }
#pragma unroll
    for (int r = 0; r < 2; r++) {
        int k = b_row + r * 16;
        Bs[0][b_col + 0][k] = __float2half(bP[r].x);
        Bs[0][b_col + 1][k] = __float2half(bP[r].y);
        Bs[0][b_col + 2][k] = __float2half(bP[r].z);
        Bs[0][b_col + 3][k] = __float2half(bP[r].w);
    }
    __syncthreads();

    for (int it = 0; it < nIter; it++) {
        int cb = it & 1;
        if (it + 1 < nIter) {
            int k0 = (it + 1) * GBK;
#pragma unroll
            for (int r = 0; r < 4; r++) {
                int m = m0 + a_row + r * 32;
                aP[r] = make_float4(0.f, 0.f, 0.f, 0.f);
                if (m < M) aP[r] = *(const float4*)(A + (size_t)m * K + k0 + a_col);
            }
#pragma unroll
            for (int r = 0; r < 2; r++)
                bP[r] = *(const float4*)(B + (size_t)(k0 + b_row + r * 16) * Nc + n0 + b_col);
        }

#pragma unroll
        for (int kk = 0; kk < GBK; kk += 16) {
            uint32_t a[2][4], b[4][2];
#pragma unroll
            for (int mi = 0; mi < 2; mi++) {
                int r0 = warp_row + mi * 16 + g;
                a[mi][0] = *(const uint32_t*)&As[cb][r0][kk + 2 * tig];
                a[mi][1] = *(const uint32_t*)&As[cb][r0 + 8][kk + 2 * tig];
                a[mi][2] = *(const uint32_t*)&As[cb][r0][kk + 2 * tig + 8];
                a[mi][3] = *(const uint32_t*)&As[cb][r0 + 8][kk + 2 * tig + 8];
            }
#pragma unroll
            for (int ni = 0; ni < 4; ni++) {
                int col = warp_col + ni * 8 + g;
                b[ni][0] = *(const uint32_t*)&Bs[cb][col][kk + 2 * tig];
                b[ni][1] = *(const uint32_t*)&Bs[cb][col][kk + 2 * tig + 8];
            }
#pragma unroll
            for (int mi = 0; mi < 2; mi++)
#pragma unroll
                for (int ni = 0; ni < 4; ni++)
                    mma_f16(c[mi][ni], a[mi], b[ni]);
        }

        if (it + 1 < nIter) {
            int nb = cb ^ 1;
#pragma unroll
            for (int r = 0; r < 4; r++) {
                int row = a_row + r * 32;
                *(__half2*)&As[nb][row][a_col]     = __floats2half2_rn(aP[r].x, aP[r].y);
                *(__half2*)&As[nb][row][a_col + 2] = __floats2half2_rn(aP[r].z, aP[r].w);
            }
#pragma unroll
            for (int r = 0; r < 2; r++) {
                int k = b_row + r * 16;
                Bs[nb][b_col + 0][k] = __float2half(bP[r].x);
                Bs[nb][b_col + 1][k] = __float2half(bP[r].y);
                Bs[nb][b_col + 2][k] = __float2half(bP[r].z);
                Bs[nb][b_col + 3][k] = __float2half(bP[r].w);
            }
            __syncthreads();
        }
    }

#pragma unroll
    for (int mi = 0; mi < 2; mi++)
#pragma unroll
        for (int ni = 0; ni < 4; ni++) {
            int row = m0 + warp_row + mi * 16 + g;
            int col = n0 + warp_col + ni * 8 + tig * 2;
            if (row < M)
                *(__half2*)(Ch + (size_t)row * Nc + col) =
                    __floats2half2_rn(c[mi][ni][0], c[mi][ni][1]);
            if (row + 8 < M)
                *(__half2*)(Ch + (size_t)(row + 8) * Nc + col) =
                    __floats2half2_rn(c[mi][ni][2], c[mi][ni][3]);
        }

    if (al != nullptr) {
        int head = blockIdx.y;
        const float* alh = al + head * 64;
        const float* arh = ar + head * 64;
        float pel[2][2], per_[2][2];
#pragma unroll
        for (int mi = 0; mi < 2; mi++) { pel[mi][0] = pel[mi][1] = per_[mi][0] = per_[mi][1] = 0.f; }
#pragma unroll
        for (int ni = 0; ni < 4; ni++) {
#pragma unroll
            for (int j = 0; j < 2; j++) {
                int col = warp_col + ni * 8 + tig * 2 + j;
                float wl = alh[col], wr = arh[col];
#pragma unroll
                for (int mi = 0; mi < 2; mi++) {
                    pel[mi][0] += c[mi][ni][j] * wl;
                    per_[mi][0] += c[mi][ni][j] * wr;
                    pel[mi][1] += c[mi][ni][2 + j] * wl;
                    per_[mi][1] += c[mi][ni][2 + j] * wr;
                }
            }
        }
#pragma unroll
        for (int off = 1; off < 4; off <<= 1) {
#pragma unroll
            for (int mi = 0; mi < 2; mi++)
#pragma unroll
                for (int rh = 0; rh < 2; rh++) {
                    pel[mi][rh] += __shfl_xor_sync(0xffffffffu, pel[mi][rh], off);
                    per_[mi][rh] += __shfl_xor_sync(0xffffffffu, per_[mi][rh], off);
                }
        }
        __syncthreads();
        float (*sred)[4] = (float (*)[4])&As[0][0][0];
        int half = warp & 1;
        if (tig == 0) {
#pragma unroll
            for (int mi = 0; mi < 2; mi++) {
#pragma unroll
                for (int rh = 0; rh < 2; rh++) {
                    int row = warp_row + mi * 16 + rh * 8 + g;
                    sred[row][half]     = pel[mi][rh];
                    sred[row][2 + half] = per_[mi][rh];
                }
            }
        }
        __syncthreads();
        if (tid < 128) {
            int m = m0 + tid;
            if (m < M) {
                el[(size_t)m * H + head] = sred[tid][0] + sred[tid][1];
                er[(size_t)m * H + head] = sred[tid][2] + sred[tid][3];
            }
        }
    }
}

// ---- layer-2 GEMM: fp16 A direct, fp16/fp32 output ----
__global__ __launch_bounds__(256)
void gemm_h_attn_kernel(const __half* __restrict__ Ah, const float* __restrict__ B,
                        float* __restrict__ C, __half* __restrict__ Ch,
                        int M, int Nc, int K,
                        const float* __restrict__ al, const float* __restrict__ ar,
                        float* __restrict__ el, float* __restrict__ er, int H) {
    __shared__ __half As[GBM][AHS];
    __shared__ __half Bs[GBN][AHS];
    int tid = threadIdx.x;
    int warp = tid >> 5, lane = tid & 31;
    int g = lane >> 2, tig = lane & 3;
    int m0 = blockIdx.x * GBM, n0 = blockIdx.y * GBN;
    int warp_row = (warp >> 1) * 32;
    int warp_col = (warp & 1) * 32;

    int ar_ = tid >> 2;
    int ac8 = (tid & 3) * 8;
    int b_row = tid >> 4;
    int b_col = (tid & 15) * 4;

    float c[2][4][4];
#pragma unroll
    for (int mi = 0; mi < 2; mi++)
#pragma unroll
        for (int ni = 0; ni < 4; ni++)
#pragma unroll
            for (int r = 0; r < 4; r++) c[mi][ni][r] = 0.f;

    for (int k0 = 0; k0 < K; k0 += GBK) {
#pragma unroll
        for (int hh = 0; hh < 2; hh++) {
            int row = ar_ + hh * 64;
            int m = m0 + row;
            uint4 u = make_uint4(0, 0, 0, 0);
            if (m < M) u = *(const uint4*)(Ah + (size_t)m * K + k0 + ac8);
            *(uint4*)&As[row][ac8] = u;
        }
#pragma unroll
        for (int r = 0; r < 2; r++) {
            int k = b_row + r * 16;
            float4 v = *(const float4*)(B + (size_t)(k0 + k) * Nc + n0 + b_col);
            Bs[b_col + 0][k] = __float2half(v.x);
            Bs[b_col + 1][k] = __float2half(v.y);
            Bs[b_col + 2][k] = __float2half(v.z);
            Bs[b_col + 3][k] = __float2half(v.w);
        }
        __syncthreads();
#pragma unroll
        for (int kk = 0; kk < GBK; kk += 16) {
            uint32_t a[2][4], b[4][2];
#pragma unroll
            for (int mi = 0; mi < 2; mi++) {
                int r0 = warp_row + mi * 16 + g;
                a[mi][0] = *(const uint32_t*)&As[r0][kk + 2 * tig];
                a[mi][1] = *(const uint32_t*)&As[r0 + 8][kk + 2 * tig];
                a[mi][2] = *(const uint32_t*)&As[r0][kk + 2 * tig + 8];
                a[mi][3] = *(const uint32_t*)&As[r0 + 8][kk + 2 * tig + 8];
            }
#pragma unroll
            for (int ni = 0; ni < 4; ni++) {
                int col = warp_col + ni * 8 + g;
                b[ni][0] = *(const uint32_t*)&Bs[col][kk + 2 * tig];
                b[ni][1] = *(const uint32_t*)&Bs[col][kk + 2 * tig + 8];
            }
#pragma unroll
            for (int mi = 0; mi < 2; mi++)
#pragma unroll
                for (int ni = 0; ni < 4; ni++)
                    mma_f16(c[mi][ni], a[mi], b[ni]);
        }
        __syncthreads();
    }

#pragma unroll
    for (int mi = 0; mi < 2; mi++)
#pragma unroll
        for (int ni = 0; ni < 4; ni++) {
            int row = m0 + warp_row + mi * 16 + g;
            int col = n0 + warp_col + ni * 8 + tig * 2;
            if (Ch != nullptr) {
                if (row < M)
                    *(__half2*)(Ch + (size_t)row * Nc + col) =
                        __floats2half2_rn(c[mi][ni][0], c[mi][ni][1]);
                if (row + 8 < M)
                    *(__half2*)(Ch + (size_t)(row + 8) * Nc + col) =
                        __floats2half2_rn(c[mi][ni][2], c[mi][ni][3]);
            } else {
                if (row < M)
                    *(float2*)(C + (size_t)row * Nc + col) =
                        make_float2(c[mi][ni][0], c[mi][ni][1]);
                if (row + 8 < M)
                    *(float2*)(C + (size_t)(row + 8) * Nc + col) =
                        make_float2(c[mi][ni][2], c[mi][ni][3]);
            }
        }

    if (al != nullptr) {
        int head = blockIdx.y;
        const float* alh = al + head * 64;
        const float* arh = ar + head * 64;
        float pel[2][2], per_[2][2];
#pragma unroll
        for (int mi = 0; mi < 2; mi++) { pel[mi][0] = pel[mi][1] = per_[mi][0] = per_[mi][1] = 0.f; }
#pragma unroll
        for (int ni = 0; ni < 4; ni++) {
#pragma unroll
            for (int j = 0; j < 2; j++) {
                int col = warp_col + ni * 8 + tig * 2 + j;
                float wl = alh[col], wr = arh[col];
#pragma unroll
                for (int mi = 0; mi < 2; mi++) {
                    pel[mi][0] += c[mi][ni][j] * wl;
                    per_[mi][0] += c[mi][ni][j] * wr;
                    pel[mi][1] += c[mi][ni][2 + j] * wl;
                    per_[mi][1] += c[mi][ni][2 + j] * wr;
                }
            }
        }
#pragma unroll
        for (int off = 1; off < 4; off <<= 1) {
#pragma unroll
            for (int mi = 0; mi < 2; mi++)
#pragma unroll
                for (int rh = 0; rh < 2; rh++) {
                    pel[mi][rh] += __shfl_xor_sync(0xffffffffu, pel[mi][rh], off);
                    per_[mi][rh] += __shfl_xor_sync(0xffffffffu, per_[mi][rh], off);
                }
        }
        __syncthreads();
        float (*sred)[4] = (float (*)[4])&As[0][0];
        int half = warp & 1;
        if (tig == 0) {
#pragma unroll
            for (int mi = 0; mi < 2; mi++) {
#pragma unroll
                for (int rh = 0; rh < 2; rh++) {
                    int row = warp_row + mi * 16 + rh * 8 + g;
                    sred[row][half]     = pel[mi][rh];
                    sred[row][2 + half] = per_[mi][rh];
                }
            }
        }
        __syncthreads();
        if (tid < 128) {
            int m = m0 + tid;
            if (m < M) {
                el[(size_t)m * H + head] = sred[tid][0] + sred[tid][1];
                er[(size_t)m * H + head] = sred[tid][2] + sred[tid][3];
            }
        }
    }
}

__device__ __forceinline__ float lrelu(float x) { return x > 0.f ? x : 0.2f * x; }

// ---------------- layer-1 aggregation: register-resident edges + shfl weights -
__global__ __launch_bounds__(256)
void aggr1_kernel(const int* __restrict__ offs, const int* __restrict__ ssrc,
                  const __half* __restrict__ fth, const float* __restrict__ el,
                  const float* __restrict__ er, const float* __restrict__ bias,
                  float* __restrict__ abuf, __half* __restrict__ h1) {
    int n = (blockIdx.x * blockDim.x + threadIdx.x) >> 5;
    int lane = threadIdx.x & 31;
    if (n >= NN) return;
    int beg = offs[n], end = offs[n + 1];
    int deg = end - beg;
    int h = lane >> 3;
    int cbase = lane * 8;
    float acc[8] = {0.f, 0.f, 0.f, 0.f, 0.f, 0.f, 0.f, 0.f};

    if (deg > 0 && deg <= 32) {
        // ---- fast path: edges & softmax numerators fully warp-resident ----
        float4 ern = *(const float4*)(er + (size_t)n * 4);
        int s_mine = 0;
        float4 ee = make_float4(0.f, 0.f, 0.f, 0.f);
        if (lane < deg) {
            s_mine = __ldg(ssrc + beg + lane);
            float4 e = *(const float4*)(el + (size_t)s_mine * 4);
            e.x = lrelu(e.x + ern.x); e.y = lrelu(e.y + ern.y);
            e.z = lrelu(e.z + ern.z); e.w = lrelu(e.w + ern.w);
            ee = make_float4(__expf(e.x), __expf(e.y), __expf(e.z), __expf(e.w));
        }
        float4 ds = ee;
#pragma unroll
        for (int o = 16; o; o >>= 1) {
            ds.x += __shfl_xor_sync(0xffffffffu, ds.x, o);
            ds.y += __shfl_xor_sync(0xffffffffu, ds.y, o);
            ds.z += __shfl_xor_sync(0xffffffffu, ds.z, o);
            ds.w += __shfl_xor_sync(0xffffffffu, ds.w, o);
        }
        float dh = (h == 0) ? ds.x : (h == 1) ? ds.y : (h == 2) ? ds.z : ds.w;
        float invh = 1.0f / dh;

        int j = 0;
        for (; j + 1 < deg; j += 2) {
            int s0 = __shfl_sync(0xffffffffu, s_mine, j);
            int s1 = __shfl_sync(0xffffffffu, s_mine, j + 1);
            // transpose softmax numerators via shfl: lane picks its head comp
            float e0x = __shfl_sync(0xffffffffu, ee.x, j);
            float e0y = __shfl_sync(0xffffffffu, ee.y, j);
            float e0z = __shfl_sync(0xffffffffu, ee.z, j);
            float e0w = __shfl_sync(0xffffffffu, ee.w, j);
            float e1x = __shfl_sync(0xffffffffu, ee.x, j + 1);
            float e1y = __shfl_sync(0xffffffffu, ee.y, j + 1);
            float e1z = __shfl_sync(0xffffffffu, ee.z, j + 1);
            float e1w = __shfl_sync(0xffffffffu, ee.w, j + 1);
            float a0 = ((h == 0) ? e0x : (h == 1) ? e0y : (h == 2) ? e0z : e0w) * invh;
            float a1 = ((h == 0) ? e1x : (h == 1) ? e1y : (h == 2) ? e1z : e1w) * invh;
            uint4 u0 = __ldg((const uint4*)(fth + (size_t)s0 * 256) + lane);
            uint4 u1 = __ldg((const uint4*)(fth + (size_t)s1 * 256) + lane);
            const __half2* h0 = (const __half2*)&u0;
            const __half2* h1p = (const __half2*)&u1;
#pragma unroll
            for (int q = 0; q < 4; q++) {
                float2 f0 = __half22float2(h0[q]);
                float2 f1 = __half22float2(h1p[q]);
                acc[2 * q]     += a0 * f0.x + a1 * f1.x;
                acc[2 * q + 1] += a0 * f0.y + a1 * f1.y;
            }
        }
        if (j < deg) {
            int s0 = __shfl_sync(0xffffffffu, s_mine, j);
            float e0x = __shfl_sync(0xffffffffu, ee.x, j);
            float e0y = __shfl_sync(0xffffffffu, ee.y, j);
            float e0z = __shfl_sync(0xffffffffu, ee.z, j);
            float e0w = __shfl_sync(0xffffffffu, ee.w, j);
            float a0 = ((h == 0) ? e0x : (h == 1) ? e0y : (h == 2) ? e0z : e0w) * invh;
            uint4 u0 = __ldg((const uint4*)(fth + (size_t)s0 * 256) + lane);
            const __half2* h0 = (const __half2*)&u0;
#pragma unroll
            for (int q = 0; q < 4; q++) {
                float2 f0 = __half22float2(h0[q]);
                acc[2 * q]     += a0 * f0.x;
                acc[2 * q + 1] += a0 * f0.y;
            }
        }
    } else if (deg > 32) {
        // ---- fallback: memory path (rare high-degree nodes) ----
        float4 ern = *(const float4*)(er + (size_t)n * 4);
        float4 ds = make_float4(0.f, 0.f, 0.f, 0.f);
        for (int i = beg + lane; i < end; i += 32) {
            int s = __ldg(ssrc + i);
            float4 e = *(const float4*)(el + (size_t)s * 4);
            e.x = lrelu(e.x + ern.x); e.y = lrelu(e.y + ern.y);
            e.z = lrelu(e.z + ern.z); e.w = lrelu(e.w + ern.w);
            float4 ee = make_float4(__expf(e.x), __expf(e.y), __expf(e.z), __expf(e.w));
            ((float4*)abuf)[i] = ee;
            ds.x += ee.x; ds.y += ee.y; ds.z += ee.z; ds.w += ee.w;
        }
#pragma unroll
        for (int o = 16; o; o >>= 1) {
            ds.x += __shfl_xor_sync(0xffffffffu, ds.x, o);
            ds.y += __shfl_xor_sync(0xffffffffu, ds.y, o);
            ds.z += __shfl_xor_sync(0xffffffffu, ds.z, o);
            ds.w += __shfl_xor_sync(0xffffffffu, ds.w, o);
        }
        float dh = (h == 0) ? ds.x : (h == 1) ? ds.y : (h == 2) ? ds.z : ds.w;
        float invh = 1.0f / dh;
        __syncwarp();
        int i = beg;
        for (; i + 1 < end; i += 2) {
            int s0 = __ldg(ssrc + i);
            int s1 = __ldg(ssrc + i + 1);
            float a0 = __ldg(abuf + (size_t)i * 4 + h) * invh;
            float a1 = __ldg(abuf + (size_t)(i + 1) * 4 + h) * invh;
            uint4 u0 = __ldg((const uint4*)(fth + (size_t)s0 * 256) + lane);
            uint4 u1 = __ldg((const uint4*)(fth + (size_t)s1 * 256) + lane);
            const __half2* h0 = (const __half2*)&u0;
            const __half2* h1p = (const __half2*)&u1;
#pragma unroll
            for (int q = 0; q < 4; q++) {
                float2 f0 = __half22float2(h0[q]);
                float2 f1 = __half22float2(h1p[q]);
                acc[2 * q]     += a0 * f0.x + a1 * f1.x;
                acc[2 * q + 1] += a0 * f0.y + a1 * f1.y;
            }
        }
        if (i < end) {
            int s0 = __ldg(ssrc + i);
            float a0 = __ldg(abuf + (size_t)i * 4 + h) * invh;
            uint4 u0 = __ldg((const uint4*)(fth + (size_t)s0 * 256) + lane);
            const __half2* h0 = (const __half2*)&u0;
#pragma unroll
            for (int q = 0; q < 4; q++) {
                float2 f0 = __half22float2(h0[q]);
                acc[2 * q]     += a0 * f0.x;
                acc[2 * q + 1] += a0 * f0.y;
            }
        }
    }
    float4 b0 = *(const float4*)(bias + cbase);
    float4 b1v = *(const float4*)(bias + cbase + 4);
    float bv[8] = {b0.x, b0.y, b0.z, b0.w, b1v.x, b1v.y, b1v.z, b1v.w};
    float o[8];
#pragma unroll
    for (int j = 0; j < 8; j++) {
        float x = acc[j] + bv[j];
        o[j] = x > 0.f ? x : expm1f(x);      // ELU
    }
    __half2 ho[4];
#pragma unroll
    for (int j = 0; j < 4; j++) ho[j] = __floats2half2_rn(o[2 * j], o[2 * j + 1]);
    *(uint4*)(h1 + (size_t)n * 256 + cbase) = *(uint4*)ho;
}

// ---------------- layer-2 aggregation: warp per node, register-resident edges -
__global__ __launch_bounds__(256)
void aggr2_kernel(const int* __restrict__ offs, const int* __restrict__ ssrc,
                  const __half* __restrict__ fth, const float* __restrict__ el,
                  const float* __restrict__ er, const float* __restrict__ res,
                  const float* __restrict__ bias, float* __restrict__ abuf,
                  float* __restrict__ out) {
    int n = (blockIdx.x * blockDim.x + threadIdx.x) >> 5;
    int lane = threadIdx.x & 31;
    if (n >= NN) return;
    int beg = offs[n], end = offs[n + 1];
    int deg = end - beg;
    float2 acc = make_float2(0.f, 0.f);

    if (deg > 0 && deg <= 32) {
        float ern = er[n];
        int s_mine = 0;
        float ee = 0.f;
        if (lane < deg) {
            s_mine = __ldg(ssrc + beg + lane);
            ee = __expf(lrelu(__ldg(el + s_mine) + ern));
        }
        float dsum = ee;
#pragma unroll
        for (int o = 16; o; o >>= 1) dsum += __shfl_xor_sync(0xffffffffu, dsum, o);
        float inv = 1.0f / dsum;

        int j = 0;
        for (; j + 1 < deg; j += 2) {
            int s0 = __shfl_sync(0xffffffffu, s_mine, j);
            int s1 = __shfl_sync(0xffffffffu, s_mine, j + 1);
            float a0 = __shfl_sync(0xffffffffu, ee, j) * inv;
            float a1 = __shfl_sync(0xffffffffu, ee, j + 1) * inv;
            __half2 v0 = __ldg((const __half2*)(fth + (size_t)s0 * 64) + lane);
            __half2 v1 = __ldg((const __half2*)(fth + (size_t)s1 * 64) + lane);
            float2 f0 = __half22float2(v0), f1 = __half22float2(v1);
            acc.x += a0 * f0.x + a1 * f1.x;
            acc.y += a0 * f0.y + a1 * f1.y;
        }
        if (j < deg) {
            int s0 = __shfl_sync(0xffffffffu, s_mine, j);
            float a0 = __shfl_sync(0xffffffffu, ee, j) * inv;
            float2 f0 = __half22float2(__ldg((const __half2*)(fth + (size_t)s0 * 64) + lane));
            acc.x += a0 * f0.x;
            acc.y += a0 * f0.y;
        }
    } else if (deg > 32) {
        float ern = er[n];
        float dsum = 0.f;
        for (int i = beg + lane; i < end; i += 32) {
            int s = __ldg(ssrc + i);
            float e = lrelu(__ldg(el + s) + ern);
            float ee = __expf(e);
            abuf[i] = ee;
            dsum += ee;
        }
#pragma unroll
        for (int o = 16; o; o >>= 1) dsum += __shfl_xor_sync(0xffffffffu, dsum, o);
        float inv = 1.0f / dsum;
        __syncwarp();
        int i = beg;
        for (; i + 1 < end; i += 2) {
            int s0 = __ldg(ssrc + i);
            int s1 = __ldg(ssrc + i + 1);
            float a0 = __ldg(abuf + i) * inv;
            float a1 = __ldg(abuf + i + 1) * inv;
            __half2 v0 = __ldg((const __half2*)(fth + (size_t)s0 * 64) + lane);
            __half2 v1 = __ldg((const __half2*)(fth + (size_t)s1 * 64) + lane);
            float2 f0 = __half22float2(v0), f1 = __half22float2(v1);
            acc.x += a0 * f0.x + a1 * f1.x;
            acc.y += a0 * f0.y + a1 * f1.y;
        }
        if (i < end) {
            int s0 = __ldg(ssrc + i);
            float a0 = __ldg(abuf + i) * inv;
            float2 f0 = __half22float2(__ldg((const __half2*)(fth + (size_t)s0 * 64) + lane));
            acc.x += a0 * f0.x;
            acc.y += a0 * f0.y;
        }
    }
    float2 r  = *(const float2*)(res + (size_t)n * 64 + lane * 2);
    float2 bb = *(const float2*)(bias + lane * 2);
    float2 o2 = make_float2(acc.x + r.x + bb.x, acc.y + r.y + bb.y);
    *(float2*)(out + (size_t)n * 64 + lane * 2) = o2;
}

// ---------------- launch ------------------------------------------------------
extern "C" void kernel_launch(void* const* d_in, const int* in_sizes, int n_in,
                              void* d_out, int out_size) {
    const float* feat  = (const float*)d_in[0];
    const int*   src   = (const int*)  d_in[1];
    const int*   dst   = (const int*)  d_in[2];
    const float* W1    = (const float*)d_in[3];
    const float* al1   = (const float*)d_in[4];
    const float* ar1   = (const float*)d_in[5];
    const float* b1    = (const float*)d_in[6];
    const float* W2    = (const float*)d_in[7];
    const float* al2   = (const float*)d_in[8];
    const float* ar2   = (const float*)d_in[9];
    const float* b2    = (const float*)d_in[10];
    const float* resW2 = (const float*)d_in[11];
    float* out = (float*)d_out;

    __half *ft1h, *ft2h, *h1h;
    float *res2, *el1, *er1, *el2, *er2, *abuf;
    int *deg, *pos, *offs, *ssrc, *bsum;
    cudaGetSymbolAddress((void**)&ft1h, g_ft1h);
    cudaGetSymbolAddress((void**)&h1h,  g_h1h);
    cudaGetSymbolAddress((void**)&ft2h, g_ft2h);
    cudaGetSymbolAddress((void**)&res2, g_res2);
    cudaGetSymbolAddress((void**)&el1,  g_el1);
    cudaGetSymbolAddress((void**)&er1,  g_er1);
    cudaGetSymbolAddress((void**)&el2,  g_el2);
    cudaGetSymbolAddress((void**)&er2,  g_er2);
    cudaGetSymbolAddress((void**)&abuf, g_abuf);
    cudaGetSymbolAddress((void**)&deg,  g_deg);
    cudaGetSymbolAddress((void**)&pos,  g_pos);
    cudaGetSymbolAddress((void**)&offs, g_offs);
    cudaGetSymbolAddress((void**)&ssrc, g_ssrc);
    cudaGetSymbolAddress((void**)&bsum, g_bsum);

    static cudaStream_t s1 = nullptr;
    static cudaEvent_t evA = nullptr, evB = nullptr, evC = nullptr, evD = nullptr;
    if (s1 == nullptr) {
        cudaStreamCreateWithFlags(&s1, cudaStreamNonBlocking);
        cudaEventCreateWithFlags(&evA, cudaEventDisableTiming);
        cudaEventCreateWithFlags(&evB, cudaEventDisableTiming);
        cudaEventCreateWithFlags(&evC, cudaEventDisableTiming);
        cudaEventCreateWithFlags(&evD, cudaEventDisableTiming);
    }

    const int TB = 256;
    const int GX = (NN + GBM - 1) / GBM;

    // ---- fork: CSR build on s1, concurrent with layer-1 GEMM on stream 0 ----
    cudaEventRecord(evA, 0);
    cudaStreamWaitEvent(s1, evA, 0);

    cudaMemsetAsync(deg, 0, NN * sizeof(int), s1);
    hist_kernel<<<(NE + TB - 1) / TB, TB, 0, s1>>>(dst, deg, pos);
    scanA_kernel<<<SCAN_NB, 256, 0, s1>>>(deg, bsum);
    scanB_kernel<<<SCAN_NB, 256, 0, s1>>>(deg, bsum, offs);
    scatter_kernel<<<(NE + TB - 1) / TB, TB, 0, s1>>>(src, dst, offs, pos, ssrc);
    cudaEventRecord(evB, s1);

    gemm_attn_kernel<<<dim3(GX, 4), TB>>>(feat, W1, ft1h, NN, 256, 256,
                                          al1, ar1, el1, er1, H1);

    // ---- join: aggr1 needs both CSR and gemm1 ----
    cudaStreamWaitEvent(0, evB, 0);
    aggr1_kernel<<<(NN * 32 + TB - 1) / TB, TB>>>(offs, ssrc, ft1h, el1, er1, b1, abuf, h1h);

    // ---- fork: residual GEMM on s1, concurrent with W2 GEMM ----
    cudaEventRecord(evC, 0);
    cudaStreamWaitEvent(s1, evC, 0);
    gemm_h_attn_kernel<<<dim3(GX, 1), TB, 0, s1>>>(h1h, resW2, res2, nullptr, NN, 64, 256,
                                                   nullptr, nullptr, nullptr, nullptr, 1);
    cudaEventRecord(evD, s1);

    gemm_h_attn_kernel<<<dim3(GX, 1), TB>>>(h1h, W2, nullptr, ft2h, NN, 64, 256,
                                            al2, ar2, el2, er2, 1);

    // ---- join: aggr2 needs ft2h/el2/er2 (s0) and res2 (s1) ----
    cudaStreamWaitEvent(0, evD, 0);
    aggr2_kernel<<<(NN * 32 + TB - 1) / TB, TB>>>(offs, ssrc, ft2h, el2, er2, res2, b2, abuf, out);
}

// round 16
// speedup vs baseline: 1.1026x; 1.0412x over previous
#include <cuda_runtime.h>
#include <cuda_fp16.h>
#include <math.h>
#include <stdint.h>

#define NN 50000
#define NE 800000
#define H1 4
#define D1 64

// ---------------- scratch (device globals; no runtime allocation) -------------
__device__ __half g_ft1h[NN * 256];
__device__ __half g_h1h [NN * 256];
__device__ __half g_ft2h[NN * 64];
__device__ float  g_res2[NN * 64];
__device__ float  g_el1[NN * 4];
__device__ float  g_er1[NN * 4];
__device__ float  g_el2[NN];
__device__ float  g_er2[NN];
__device__ int    g_deg[NN];
__device__ int    g_pos[NE];
__device__ int    g_offs[NN + 1];
__device__ int    g_bsum[128];
__device__ int    g_ssrc[NE];
__device__ float  g_abuf[NE * 4];

#define SCAN_NB ((NN + 511) / 512)

// ---------------- CSR build kernels (x4 vectorized hist/scatter) ---------------
__global__ void hist_kernel(const int4* __restrict__ dst4, int* __restrict__ deg,
                            int4* __restrict__ pos4) {
    int e = blockIdx.x * blockDim.x + threadIdx.x;
    if (e < NE / 4) {
        int4 d = __ldg(dst4 + e);
        int4 p;
        p.x = atomicAdd(&deg[d.x], 1);
        p.y = atomicAdd(&deg[d.y], 1);
        p.z = atomicAdd(&deg[d.z], 1);
        p.w = atomicAdd(&deg[d.w], 1);
        pos4[e] = p;
    }
}

__global__ void scanA_kernel(const int* __restrict__ deg, int* __restrict__ bsum) {
    __shared__ int sm[256];
    int b = blockIdx.x, t = threadIdx.x;
    int i0 = b * 512 + t, i1 = i0 + 256;
    int v = 0;
    if (i0 < NN) v += deg[i0];
    if (i1 < NN) v += deg[i1];
    sm[t] = v;
    __syncthreads();
#pragma unroll
    for (int o = 128; o; o >>= 1) { if (t < o) sm[t] += sm[t + o]; __syncthreads(); }
    if (t == 0) bsum[b] = sm[0];
}

__global__ void scanB_kernel(const int* __restrict__ deg, const int* __restrict__ bsum,
                             int* __restrict__ offs) {
    __shared__ int sb[128];
    __shared__ int sm[256];
    int b = blockIdx.x, t = threadIdx.x;

    if (t < 128) sb[t] = (t < SCAN_NB) ? bsum[t] : 0;
    __syncthreads();
#pragma unroll
    for (int o = 1; o < 128; o <<= 1) {
        int x = 0;
        if (t < 128 && t >= o) x = sb[t - o];
        __syncthreads();
        if (t < 128) sb[t] += x;
        __syncthreads();
    }
    int bprefix = (b == 0) ? 0 : sb[b - 1];

    int i = b * 512 + t * 2;
    int d0 = (i < NN) ? deg[i] : 0;
    int d1 = (i + 1 < NN) ? deg[i + 1] : 0;
    int s = d0 + d1;
    sm[t] = s;
    __syncthreads();
#pragma unroll
    for (int o = 1; o < 256; o <<= 1) {
        int x = (t >= o) ? sm[t - o] : 0;
        __syncthreads();
        sm[t] += x;
        __syncthreads();
    }
    int ex = sm[t] - s + bprefix;
    if (i < NN) offs[i] = ex;
    if (i + 1 < NN) offs[i + 1] = ex + d0;
    if (b == 0 && t == 0) offs[NN] = NE;
}

__global__ void scatter_kernel(const int4* __restrict__ src4, const int4* __restrict__ dst4,
                               const int* __restrict__ offs, const int4* __restrict__ pos4,
                               int* __restrict__ ssrc) {
    int e = blockIdx.x * blockDim.x + threadIdx.x;
    if (e < NE / 4) {
        int4 s = __ldg(src4 + e);
        int4 d = __ldg(dst4 + e);
        int4 p = __ldg(pos4 + e);
        ssrc[__ldg(offs + d.x) + p.x] = s.x;
        ssrc[__ldg(offs + d.y) + p.y] = s.y;
        ssrc[__ldg(offs + d.z) + p.z] = s.z;
        ssrc[__ldg(offs + d.w) + p.w] = s.w;
    }
}

// ---------------- fp16 tensor-core GEMM with fused attn epilogue --------------
#define GBM 128
#define GBN 64
#define GBK 32
#define AHS 40

__device__ __forceinline__ void mma_f16(float* c, const uint32_t* a, const uint32_t* b) {
    asm volatile(
        "mma.sync.aligned.m16n8k16.row.col.f32.f16.f16.f32 "
        "{%0,%1,%2,%3}, {%4,%5,%6,%7}, {%8,%9}, {%0,%1,%2,%3};\n"
        : "+f"(c[0]), "+f"(c[1]), "+f"(c[2]), "+f"(c[3])
        : "r"(a[0]), "r"(a[1]), "r"(a[2]), "r"(a[3]), "r"(b[0]), "r"(b[1]));
}

// ---- layer-1 GEMM: fp32 A, double-buffered half tiles ----
__global__ __launch_bounds__(256)
void gemm_attn_kernel(const float* __restrict__ A, const float* __restrict__ B,
                      __half* __restrict__ Ch,
                      int M, int Nc, int K,
                      const float* __restrict__ al, const float* __restrict__ ar,
                      float* __restrict__ el, float* __restrict__ er, int H) {
    __shared__ __half As[2][GBM][AHS];
    __shared__ __half Bs[2][GBN][AHS];

    int tid = threadIdx.x;
    int warp = tid >> 5, lane = tid & 31;
    int g = lane >> 2, tig = lane & 3;
    int m0 = blockIdx.x * GBM, n0 = blockIdx.y * GBN;
    int warp_row = (warp >> 1) * 32;
    int warp_col = (warp & 1) * 32;

    int a_row = tid >> 3;
    int a_col = (tid & 7) * 4;
    int b_row = tid >> 4;
    int b_col = (tid & 15) * 4;

    float c[2][4][4];
#pragma unroll
    for (int mi = 0; mi < 2; mi++)
#pragma unroll
        for (int ni = 0; ni < 4; ni++)
#pragma unroll
            for (int r = 0; r < 4; r++) c[mi][ni][r] = 0.f;

    const int nIter = K / GBK;
    float4 aP[4];
    float4 bP[2];

#pragma unroll
    for (int r = 0; r < 4; r++) {
        int m = m0 + a_row + r * 32;
        aP[r] = make_float4(0.f, 0.f, 0.f, 0.f);
        if (m < M) aP[r] = *(const float4*)(A + (size_t)m * K + a_col);
    }
#pragma unroll
    for (int r = 0; r < 2; r++)
        bP[r] = *(const float4*)(B + (size_t)(b_row + r * 16) * Nc + n0 + b_col);

#pragma unroll
    for (int r = 0; r < 4; r++) {
        int row = a_row + r * 32;
        *(__half2*)&As[0][row][a_col]     = __floats2half2_rn(aP[r].x, aP[r].y);
        *(__half2*)&As[0][row][a_col + 2] = __floats2half2_rn(aP[r].z, aP[r].w);
    }
#pragma unroll
    for (int r = 0; r < 2; r++) {
        int k = b_row + r * 16;
        Bs[0][b_col + 0][k] = __float2half(bP[r].x);
        Bs[0][b_col + 1][k] = __float2half(bP[r].y);
        Bs[0][b_col + 2][k] = __float2half(bP[r].z);
        Bs[0][b_col + 3][k] = __float2half(bP[r].w);
    }
    __syncthreads();

    for (int it = 0; it < nIter; it++) {
        int cb = it & 1;
        if (it + 1 < nIter) {
            int k0 = (it + 1) * GBK;
#pragma unroll
            for (int r = 0; r < 4; r++) {
                int m = m0 + a_row + r * 32;
                aP[r] = make_float4(0.f, 0.f, 0.f, 0.f);
                if (m < M) aP[r] = *(const float4*)(A + (size_t)m * K + k0 + a_col);
            }
#pragma unroll
            for (int r = 0; r < 2; r++)
                bP[r] = *(const float4*)(B + (size_t)(k0 + b_row + r * 16) * Nc + n0 + b_col);
        }

#pragma unroll
        for (int kk = 0; kk < GBK; kk += 16) {
            uint32_t a[2][4], b[4][2];
#pragma unroll
            for (int mi = 0; mi < 2; mi++) {
                int r0 = warp_row + mi * 16 + g;
                a[mi][0] = *(const uint32_t*)&As[cb][r0][kk + 2 * tig];
                a[mi][1] = *(const uint32_t*)&As[cb][r0 + 8][kk + 2 * tig];
                a[mi][2] = *(const uint32_t*)&As[cb][r0][kk + 2 * tig + 8];
                a[mi][3] = *(const uint32_t*)&As[cb][r0 + 8][kk + 2 * tig + 8];
            }
#pragma unroll
            for (int ni = 0; ni < 4; ni++) {
                int col = warp_col + ni * 8 + g;
                b[ni][0] = *(const uint32_t*)&Bs[cb][col][kk + 2 * tig];
                b[ni][1] = *(const uint32_t*)&Bs[cb][col][kk + 2 * tig + 8];
            }
#pragma unroll
            for (int mi = 0; mi < 2; mi++)
#pragma unroll
                for (int ni = 0; ni < 4; ni++)
                    mma_f16(c[mi][ni], a[mi], b[ni]);
        }

        if (it + 1 < nIter) {
            int nb = cb ^ 1;
#pragma unroll
            for (int r = 0; r < 4; r++) {
                int row = a_row + r * 32;
                *(__half2*)&As[nb][row][a_col]     = __floats2half2_rn(aP[r].x, aP[r].y);
                *(__half2*)&As[nb][row][a_col + 2] = __floats2half2_rn(aP[r].z, aP[r].w);
            }
#pragma unroll
            for (int r = 0; r < 2; r++) {
                int k = b_row + r * 16;
                Bs[nb][b_col + 0][k] = __float2half(bP[r].x);
                Bs[nb][b_col + 1][k] = __float2half(bP[r].y);
                Bs[nb][b_col + 2][k] = __float2half(bP[r].z);
                Bs[nb][b_col + 3][k] = __float2half(bP[r].w);
            }
            __syncthreads();
        }
    }

#pragma unroll
    for (int mi = 0; mi < 2; mi++)
#pragma unroll
        for (int ni = 0; ni < 4; ni++) {
            int row = m0 + warp_row + mi * 16 + g;
            int col = n0 + warp_col + ni * 8 + tig * 2;
            if (row < M)
                *(__half2*)(Ch + (size_t)row * Nc + col) =
                    __floats2half2_rn(c[mi][ni][0], c[mi][ni][1]);
            if (row + 8 < M)
                *(__half2*)(Ch + (size_t)(row + 8) * Nc + col) =
                    __floats2half2_rn(c[mi][ni][2], c[mi][ni][3]);
        }

    if (al != nullptr) {
        int head = blockIdx.y;
        const float* alh = al + head * 64;
        const float* arh = ar + head * 64;
        float pel[2][2], per_[2][2];
#pragma unroll
        for (int mi = 0; mi < 2; mi++) { pel[mi][0] = pel[mi][1] = per_[mi][0] = per_[mi][1] = 0.f; }
#pragma unroll
        for (int ni = 0; ni < 4; ni++) {
#pragma unroll
            for (int j = 0; j < 2; j++) {
                int col = warp_col + ni * 8 + tig * 2 + j;
                float wl = alh[col], wr = arh[col];
#pragma unroll
                for (int mi = 0; mi < 2; mi++) {
                    pel[mi][0] += c[mi][ni][j] * wl;
                    per_[mi][0] += c[mi][ni][j] * wr;
                    pel[mi][1] += c[mi][ni][2 + j] * wl;
                    per_[mi][1] += c[mi][ni][2 + j] * wr;
                }
            }
        }
#pragma unroll
        for (int off = 1; off < 4; off <<= 1) {
#pragma unroll
            for (int mi = 0; mi < 2; mi++)
#pragma unroll
                for (int rh = 0; rh < 2; rh++) {
                    pel[mi][rh] += __shfl_xor_sync(0xffffffffu, pel[mi][rh], off);
                    per_[mi][rh] += __shfl_xor_sync(0xffffffffu, per_[mi][rh], off);
                }
        }
        __syncthreads();
        float (*sred)[4] = (float (*)[4])&As[0][0][0];
        int half = warp & 1;
        if (tig == 0) {
#pragma unroll
            for (int mi = 0; mi < 2; mi++) {
#pragma unroll
                for (int rh = 0; rh < 2; rh++) {
                    int row = warp_row + mi * 16 + rh * 8 + g;
                    sred[row][half]     = pel[mi][rh];
                    sred[row][2 + half] = per_[mi][rh];
                }
            }
        }
        __syncthreads();
        if (tid < 128) {
            int m = m0 + tid;
            if (m < M) {
                el[(size_t)m * H + head] = sred[tid][0] + sred[tid][1];
                er[(size_t)m * H + head] = sred[tid][2] + sred[tid][3];
            }
        }
    }
}

// ---- layer-2 GEMM: fp16 A direct, fp16/fp32 output ----
__global__ __launch_bounds__(256)
void gemm_h_attn_kernel(const __half* __restrict__ Ah, const float* __restrict__ B,
                        float* __restrict__ C, __half* __restrict__ Ch,
                        int M, int Nc, int K,
                        const float* __restrict__ al, const float* __restrict__ ar,
                        float* __restrict__ el, float* __restrict__ er, int H) {
    __shared__ __half As[GBM][AHS];
    __shared__ __half Bs[GBN][AHS];
    int tid = threadIdx.x;
    int warp = tid >> 5, lane = tid & 31;
    int g = lane >> 2, tig = lane & 3;
    int m0 = blockIdx.x * GBM, n0 = blockIdx.y * GBN;
    int warp_row = (warp >> 1) * 32;
    int warp_col = (warp & 1) * 32;

    int ar_ = tid >> 2;
    int ac8 = (tid & 3) * 8;
    int b_row = tid >> 4;
    int b_col = (tid & 15) * 4;

    float c[2][4][4];
#pragma unroll
    for (int mi = 0; mi < 2; mi++)
#pragma unroll
        for (int ni = 0; ni < 4; ni++)
#pragma unroll
            for (int r = 0; r < 4; r++) c[mi][ni][r] = 0.f;

    for (int k0 = 0; k0 < K; k0 += GBK) {
#pragma unroll
        for (int hh = 0; hh < 2; hh++) {
            int row = ar_ + hh * 64;
            int m = m0 + row;
            uint4 u = make_uint4(0, 0, 0, 0);
            if (m < M) u = *(const uint4*)(Ah + (size_t)m * K + k0 + ac8);
            *(uint4*)&As[row][ac8] = u;
        }
#pragma unroll
        for (int r = 0; r < 2; r++) {
            int k = b_row + r * 16;
            float4 v = *(const float4*)(B + (size_t)(k0 + k) * Nc + n0 + b_col);
            Bs[b_col + 0][k] = __float2half(v.x);
            Bs[b_col + 1][k] = __float2half(v.y);
            Bs[b_col + 2][k] = __float2half(v.z);
            Bs[b_col + 3][k] = __float2half(v.w);
        }
        __syncthreads();
#pragma unroll
        for (int kk = 0; kk < GBK; kk += 16) {
            uint32_t a[2][4], b[4][2];
#pragma unroll
            for (int mi = 0; mi < 2; mi++) {
                int r0 = warp_row + mi * 16 + g;
                a[mi][0] = *(const uint32_t*)&As[r0][kk + 2 * tig];
                a[mi][1] = *(const uint32_t*)&As[r0 + 8][kk + 2 * tig];
                a[mi][2] = *(const uint32_t*)&As[r0][kk + 2 * tig + 8];
                a[mi][3] = *(const uint32_t*)&As[r0 + 8][kk + 2 * tig + 8];
            }
#pragma unroll
            for (int ni = 0; ni < 4; ni++) {
                int col = warp_col + ni * 8 + g;
                b[ni][0] = *(const uint32_t*)&Bs[col][kk + 2 * tig];
                b[ni][1] = *(const uint32_t*)&Bs[col][kk + 2 * tig + 8];
            }
#pragma unroll
            for (int mi = 0; mi < 2; mi++)
#pragma unroll
                for (int ni = 0; ni < 4; ni++)
                    mma_f16(c[mi][ni], a[mi], b[ni]);
        }
        __syncthreads();
    }

#pragma unroll
    for (int mi = 0; mi < 2; mi++)
#pragma unroll
        for (int ni = 0; ni < 4; ni++) {
            int row = m0 + warp_row + mi * 16 + g;
            int col = n0 + warp_col + ni * 8 + tig * 2;
            if (Ch != nullptr) {
                if (row < M)
                    *(__half2*)(Ch + (size_t)row * Nc + col) =
                        __floats2half2_rn(c[mi][ni][0], c[mi][ni][1]);
                if (row + 8 < M)
                    *(__half2*)(Ch + (size_t)(row + 8) * Nc + col) =
                        __floats2half2_rn(c[mi][ni][2], c[mi][ni][3]);
            } else {
                if (row < M)
                    *(float2*)(C + (size_t)row * Nc + col) =
                        make_float2(c[mi][ni][0], c[mi][ni][1]);
                if (row + 8 < M)
                    *(float2*)(C + (size_t)(row + 8) * Nc + col) =
                        make_float2(c[mi][ni][2], c[mi][ni][3]);
            }
        }

    if (al != nullptr) {
        int head = blockIdx.y;
        const float* alh = al + head * 64;
        const float* arh = ar + head * 64;
        float pel[2][2], per_[2][2];
#pragma unroll
        for (int mi = 0; mi < 2; mi++) { pel[mi][0] = pel[mi][1] = per_[mi][0] = per_[mi][1] = 0.f; }
#pragma unroll
        for (int ni = 0; ni < 4; ni++) {
#pragma unroll
            for (int j = 0; j < 2; j++) {
                int col = warp_col + ni * 8 + tig * 2 + j;
                float wl = alh[col], wr = arh[col];
#pragma unroll
                for (int mi = 0; mi < 2; mi++) {
                    pel[mi][0] += c[mi][ni][j] * wl;
                    per_[mi][0] += c[mi][ni][j] * wr;
                    pel[mi][1] += c[mi][ni][2 + j] * wl;
                    per_[mi][1] += c[mi][ni][2 + j] * wr;
                }
            }
        }
#pragma unroll
        for (int off = 1; off < 4; off <<= 1) {
#pragma unroll
            for (int mi = 0; mi < 2; mi++)
#pragma unroll
                for (int rh = 0; rh < 2; rh++) {
                    pel[mi][rh] += __shfl_xor_sync(0xffffffffu, pel[mi][rh], off);
                    per_[mi][rh] += __shfl_xor_sync(0xffffffffu, per_[mi][rh], off);
                }
        }
        __syncthreads();
        float (*sred)[4] = (float (*)[4])&As[0][0];
        int half = warp & 1;
        if (tig == 0) {
#pragma unroll
            for (int mi = 0; mi < 2; mi++) {
#pragma unroll
                for (int rh = 0; rh < 2; rh++) {
                    int row = warp_row + mi * 16 + rh * 8 + g;
                    sred[row][half]     = pel[mi][rh];
                    sred[row][2 + half] = per_[mi][rh];
                }
            }
        }
        __syncthreads();
        if (tid < 128) {
            int m = m0 + tid;
            if (m < M) {
                el[(size_t)m * H + head] = sred[tid][0] + sred[tid][1];
                er[(size_t)m * H + head] = sred[tid][2] + sred[tid][3];
            }
        }
    }
}

__device__ __forceinline__ float lrelu(float x) { return x > 0.f ? x : 0.2f * x; }

// ---------------- layer-1 aggregation (R12-best): reg edges + abuf weights ----
__global__ __launch_bounds__(256)
void aggr1_kernel(const int* __restrict__ offs, const int* __restrict__ ssrc,
                  const __half* __restrict__ fth, const float* __restrict__ el,
                  const float* __restrict__ er, const float* __restrict__ bias,
                  float* __restrict__ abuf, __half* __restrict__ h1) {
    int n = (blockIdx.x * blockDim.x + threadIdx.x) >> 5;
    int lane = threadIdx.x & 31;
    if (n >= NN) return;
    int beg = offs[n], end = offs[n + 1];
    int deg = end - beg;
    int h = lane >> 3;
    int cbase = lane * 8;
    float acc[8] = {0.f, 0.f, 0.f, 0.f, 0.f, 0.f, 0.f, 0.f};

    if (deg > 0 && deg <= 32) {
        float4 ern = *(const float4*)(er + (size_t)n * 4);
        int s_mine = 0;
        float4 ee = make_float4(0.f, 0.f, 0.f, 0.f);
        if (lane < deg) {
            s_mine = __ldg(ssrc + beg + lane);
            float4 e = *(const float4*)(el + (size_t)s_mine * 4);
            e.x = lrelu(e.x + ern.x); e.y = lrelu(e.y + ern.y);
            e.z = lrelu(e.z + ern.z); e.w = lrelu(e.w + ern.w);
            ee = make_float4(__expf(e.x), __expf(e.y), __expf(e.z), __expf(e.w));
            ((float4*)abuf)[beg + lane] = ee;
        }
        float4 ds = ee;
#pragma unroll
        for (int o = 16; o; o >>= 1) {
            ds.x += __shfl_xor_sync(0xffffffffu, ds.x, o);
            ds.y += __shfl_xor_sync(0xffffffffu, ds.y, o);
            ds.z += __shfl_xor_sync(0xffffffffu, ds.z, o);
            ds.w += __shfl_xor_sync(0xffffffffu, ds.w, o);
        }
        float dh = (h == 0) ? ds.x : (h == 1) ? ds.y : (h == 2) ? ds.z : ds.w;
        float invh = 1.0f / dh;
        __syncwarp();

        int j = 0;
        for (; j + 1 < deg; j += 2) {
            int s0 = __shfl_sync(0xffffffffu, s_mine, j);
            int s1 = __shfl_sync(0xffffffffu, s_mine, j + 1);
            float a0 = __ldg(abuf + (size_t)(beg + j) * 4 + h) * invh;
            float a1 = __ldg(abuf + (size_t)(beg + j + 1) * 4 + h) * invh;
            uint4 u0 = __ldg((const uint4*)(fth + (size_t)s0 * 256) + lane);
            uint4 u1 = __ldg((const uint4*)(fth + (size_t)s1 * 256) + lane);
            const __half2* h0 = (const __half2*)&u0;
            const __half2* h1p = (const __half2*)&u1;
#pragma unroll
            for (int q = 0; q < 4; q++) {
                float2 f0 = __half22float2(h0[q]);
                float2 f1 = __half22float2(h1p[q]);
                acc[2 * q]     += a0 * f0.x + a1 * f1.x;
                acc[2 * q + 1] += a0 * f0.y + a1 * f1.y;
            }
        }
        if (j < deg) {
            int s0 = __shfl_sync(0xffffffffu, s_mine, j);
            float a0 = __ldg(abuf + (size_t)(beg + j) * 4 + h) * invh;
            uint4 u0 = __ldg((const uint4*)(fth + (size_t)s0 * 256) + lane);
            const __half2* h0 = (const __half2*)&u0;
#pragma unroll
            for (int q = 0; q < 4; q++) {
                float2 f0 = __half22float2(h0[q]);
                acc[2 * q]     += a0 * f0.x;
                acc[2 * q + 1] += a0 * f0.y;
            }
        }
    } else if (deg > 32) {
        float4 ern = *(const float4*)(er + (size_t)n * 4);
        float4 ds = make_float4(0.f, 0.f, 0.f, 0.f);
        for (int i = beg + lane; i < end; i += 32) {
            int s = __ldg(ssrc + i);
            float4 e = *(const float4*)(el + (size_t)s * 4);
            e.x = lrelu(e.x + ern.x); e.y = lrelu(e.y + ern.y);
            e.z = lrelu(e.z + ern.z); e.w = lrelu(e.w + ern.w);
            float4 ee = make_float4(__expf(e.x), __expf(e.y), __expf(e.z), __expf(e.w));
            ((float4*)abuf)[i] = ee;
            ds.x += ee.x; ds.y += ee.y; ds.z += ee.z; ds.w += ee.w;
        }
#pragma unroll
        for (int o = 16; o; o >>= 1) {
            ds.x += __shfl_xor_sync(0xffffffffu, ds.x, o);
            ds.y += __shfl_xor_sync(0xffffffffu, ds.y, o);
            ds.z += __shfl_xor_sync(0xffffffffu, ds.z, o);
            ds.w += __shfl_xor_sync(0xffffffffu, ds.w, o);
        }
        float dh = (h == 0) ? ds.x : (h == 1) ? ds.y : (h == 2) ? ds.z : ds.w;
        float invh = 1.0f / dh;
        __syncwarp();
        int i = beg;
        for (; i + 1 < end; i += 2) {
            int s0 = __ldg(ssrc + i);
            int s1 = __ldg(ssrc + i + 1);
            float a0 = __ldg(abuf + (size_t)i * 4 + h) * invh;
            float a1 = __ldg(abuf + (size_t)(i + 1) * 4 + h) * invh;
            uint4 u0 = __ldg((const uint4*)(fth + (size_t)s0 * 256) + lane);
            uint4 u1 = __ldg((const uint4*)(fth + (size_t)s1 * 256) + lane);
            const __half2* h0 = (const __half2*)&u0;
            const __half2* h1p = (const __half2*)&u1;
#pragma unroll
            for (int q = 0; q < 4; q++) {
                float2 f0 = __half22float2(h0[q]);
                float2 f1 = __half22float2(h1p[q]);
                acc[2 * q]     += a0 * f0.x + a1 * f1.x;
                acc[2 * q + 1] += a0 * f0.y + a1 * f1.y;
            }
        }
        if (i < end) {
            int s0 = __ldg(ssrc + i);
            float a0 = __ldg(abuf + (size_t)i * 4 + h) * invh;
            uint4 u0 = __ldg((const uint4*)(fth + (size_t)s0 * 256) + lane);
            const __half2* h0 = (const __half2*)&u0;
#pragma unroll
            for (int q = 0; q < 4; q++) {
                float2 f0 = __half22float2(h0[q]);
                acc[2 * q]     += a0 * f0.x;
                acc[2 * q + 1] += a0 * f0.y;
            }
        }
    }
    float4 b0 = *(const float4*)(bias + cbase);
    float4 b1v = *(const float4*)(bias + cbase + 4);
    float bv[8] = {b0.x, b0.y, b0.z, b0.w, b1v.x, b1v.y, b1v.z, b1v.w};
    float o[8];
#pragma unroll
    for (int j = 0; j < 8; j++) {
        float x = acc[j] + bv[j];
        o[j] = x > 0.f ? x : expm1f(x);      // ELU
    }
    __half2 ho[4];
#pragma unroll
    for (int j = 0; j < 4; j++) ho[j] = __floats2half2_rn(o[2 * j], o[2 * j + 1]);
    *(uint4*)(h1 + (size_t)n * 256 + cbase) = *(uint4*)ho;
}

// ---------------- layer-2 aggregation: warp per node, register-resident edges -
__global__ __launch_bounds__(256)
void aggr2_kernel(const int* __restrict__ offs, const int* __restrict__ ssrc,
                  const __half* __restrict__ fth, const float* __restrict__ el,
                  const float* __restrict__ er, const float* __restrict__ res,
                  const float* __restrict__ bias, float* __restrict__ abuf,
                  float* __restrict__ out) {
    int n = (blockIdx.x * blockDim.x + threadIdx.x) >> 5;
    int lane = threadIdx.x & 31;
    if (n >= NN) return;
    int beg = offs[n], end = offs[n + 1];
    int deg = end - beg;
    float2 acc = make_float2(0.f, 0.f);

    if (deg > 0 && deg <= 32) {
        float ern = er[n];
        int s_mine = 0;
        float ee = 0.f;
        if (lane < deg) {
            s_mine = __ldg(ssrc + beg + lane);
            ee = __expf(lrelu(__ldg(el + s_mine) + ern));
        }
        float dsum = ee;
#pragma unroll
        for (int o = 16; o; o >>= 1) dsum += __shfl_xor_sync(0xffffffffu, dsum, o);
        float inv = 1.0f / dsum;

        int j = 0;
        for (; j + 1 < deg; j += 2) {
            int s0 = __shfl_sync(0xffffffffu, s_mine, j);
            int s1 = __shfl_sync(0xffffffffu, s_mine, j + 1);
            float a0 = __shfl_sync(0xffffffffu, ee, j) * inv;
            float a1 = __shfl_sync(0xffffffffu, ee, j + 1) * inv;
            __half2 v0 = __ldg((const __half2*)(fth + (size_t)s0 * 64) + lane);
            __half2 v1 = __ldg((const __half2*)(fth + (size_t)s1 * 64) + lane);
            float2 f0 = __half22float2(v0), f1 = __half22float2(v1);
            acc.x += a0 * f0.x + a1 * f1.x;
            acc.y += a0 * f0.y + a1 * f1.y;
        }
        if (j < deg) {
            int s0 = __shfl_sync(0xffffffffu, s_mine, j);
            float a0 = __shfl_sync(0xffffffffu, ee, j) * inv;
            float2 f0 = __half22float2(__ldg((const __half2*)(fth + (size_t)s0 * 64) + lane));
            acc.x += a0 * f0.x;
            acc.y += a0 * f0.y;
        }
    } else if (deg > 32) {
        float ern = er[n];
        float dsum = 0.f;
        for (int i = beg + lane; i < end; i += 32) {
            int s = __ldg(ssrc + i);
            float e = lrelu(__ldg(el + s) + ern);
            float ee = __expf(e);
            abuf[i] = ee;
            dsum += ee;
        }
#pragma unroll
        for (int o = 16; o; o >>= 1) dsum += __shfl_xor_sync(0xffffffffu, dsum, o);
        float inv = 1.0f / dsum;
        __syncwarp();
        int i = beg;
        for (; i + 1 < end; i += 2) {
            int s0 = __ldg(ssrc + i);
            int s1 = __ldg(ssrc + i + 1);
            float a0 = __ldg(abuf + i) * inv;
            float a1 = __ldg(abuf + i + 1) * inv;
            __half2 v0 = __ldg((const __half2*)(fth + (size_t)s0 * 64) + lane);
            __half2 v1 = __ldg((const __half2*)(fth + (size_t)s1 * 64) + lane);
            float2 f0 = __half22float2(v0), f1 = __half22float2(v1);
            acc.x += a0 * f0.x + a1 * f1.x;
            acc.y += a0 * f0.y + a1 * f1.y;
        }
        if (i < end) {
            int s0 = __ldg(ssrc + i);
            float a0 = __ldg(abuf + i) * inv;
            float2 f0 = __half22float2(__ldg((const __half2*)(fth + (size_t)s0 * 64) + lane));
            acc.x += a0 * f0.x;
            acc.y += a0 * f0.y;
        }
    }
    float2 r  = *(const float2*)(res + (size_t)n * 64 + lane * 2);
    float2 bb = *(const float2*)(bias + lane * 2);
    float2 o2 = make_float2(acc.x + r.x + bb.x, acc.y + r.y + bb.y);
    *(float2*)(out + (size_t)n * 64 + lane * 2) = o2;
}

// ---------------- launch ------------------------------------------------------
extern "C" void kernel_launch(void* const* d_in, const int* in_sizes, int n_in,
                              void* d_out, int out_size) {
    const float* feat  = (const float*)d_in[0];
    const int*   src   = (const int*)  d_in[1];
    const int*   dst   = (const int*)  d_in[2];
    const float* W1    = (const float*)d_in[3];
    const float* al1   = (const float*)d_in[4];
    const float* ar1   = (const float*)d_in[5];
    const float* b1    = (const float*)d_in[6];
    const float* W2    = (const float*)d_in[7];
    const float* al2   = (const float*)d_in[8];
    const float* ar2   = (const float*)d_in[9];
    const float* b2    = (const float*)d_in[10];
    const float* resW2 = (const float*)d_in[11];
    float* out = (float*)d_out;

    __half *ft1h, *ft2h, *h1h;
    float *res2, *el1, *er1, *el2, *er2, *abuf;
    int *deg, *pos, *offs, *ssrc, *bsum;
    cudaGetSymbolAddress((void**)&ft1h, g_ft1h);
    cudaGetSymbolAddress((void**)&h1h,  g_h1h);
    cudaGetSymbolAddress((void**)&ft2h, g_ft2h);
    cudaGetSymbolAddress((void**)&res2, g_res2);
    cudaGetSymbolAddress((void**)&el1,  g_el1);
    cudaGetSymbolAddress((void**)&er1,  g_er1);
    cudaGetSymbolAddress((void**)&el2,  g_el2);
    cudaGetSymbolAddress((void**)&er2,  g_er2);
    cudaGetSymbolAddress((void**)&abuf, g_abuf);
    cudaGetSymbolAddress((void**)&deg,  g_deg);
    cudaGetSymbolAddress((void**)&pos,  g_pos);
    cudaGetSymbolAddress((void**)&offs, g_offs);
    cudaGetSymbolAddress((void**)&ssrc, g_ssrc);
    cudaGetSymbolAddress((void**)&bsum, g_bsum);

    static cudaStream_t s1 = nullptr;
    static cudaEvent_t evA = nullptr, evB = nullptr, evC = nullptr, evD = nullptr;
    if (s1 == nullptr) {
        cudaStreamCreateWithFlags(&s1, cudaStreamNonBlocking);
        cudaEventCreateWithFlags(&evA, cudaEventDisableTiming);
        cudaEventCreateWithFlags(&evB, cudaEventDisableTiming);
        cudaEventCreateWithFlags(&evC, cudaEventDisableTiming);
        cudaEventCreateWithFlags(&evD, cudaEventDisableTiming);
    }

    const int TB = 256;
    const int GX = (NN + GBM - 1) / GBM;
    const int NE4 = NE / 4;

    // ---- fork: CSR build on s1, concurrent with layer-1 GEMM on stream 0 ----
    cudaEventRecord(evA, 0);
    cudaStreamWaitEvent(s1, evA, 0);

    cudaMemsetAsync(deg, 0, NN * sizeof(int), s1);
    hist_kernel<<<(NE4 + TB - 1) / TB, TB, 0, s1>>>((const int4*)dst, deg, (int4*)pos);
    scanA_kernel<<<SCAN_NB, 256, 0, s1>>>(deg, bsum);
    scanB_kernel<<<SCAN_NB, 256, 0, s1>>>(deg, bsum, offs);
    scatter_kernel<<<(NE4 + TB - 1) / TB, TB, 0, s1>>>((const int4*)src, (const int4*)dst,
                                                       offs, (const int4*)pos, ssrc);
    cudaEventRecord(evB, s1);

    gemm_attn_kernel<<<dim3(GX, 4), TB>>>(feat, W1, ft1h, NN, 256, 256,
                                          al1, ar1, el1, er1, H1);

    // ---- join: aggr1 needs both CSR and gemm1 ----
    cudaStreamWaitEvent(0, evB, 0);
    aggr1_kernel<<<(NN * 32 + TB - 1) / TB, TB>>>(offs, ssrc, ft1h, el1, er1, b1, abuf, h1h);

    // ---- fork: residual GEMM on s1, concurrent with W2 GEMM ----
    cudaEventRecord(evC, 0);
    cudaStreamWaitEvent(s1, evC, 0);
    gemm_h_attn_kernel<<<dim3(GX, 1), TB, 0, s1>>>(h1h, resW2, res2, nullptr, NN, 64, 256,
                                                   nullptr, nullptr, nullptr, nullptr, 1);
    cudaEventRecord(evD, s1);

    gemm_h_attn_kernel<<<dim3(GX, 1), TB>>>(h1h, W2, nullptr, ft2h, NN, 64, 256,
                                            al2, ar2, el2, er2, 1);

    // ---- join: aggr2 needs ft2h/el2/er2 (s0) and res2 (s1) ----
    cudaStreamWaitEvent(0, evD, 0);
    aggr2_kernel<<<(NN * 32 + TB - 1) / TB, TB>>>(offs, ssrc, ft2h, el2, er2, res2, b2, abuf, out);
}